// round 10
// baseline (speedup 1.0000x reference)
#include <cuda_runtime.h>
#include <math.h>
#include <stdint.h>

#define DINL __device__ __forceinline__

// ---------- packed fp32x2 helpers (sm_103a) ----------
DINL unsigned long long pack2(float x, float y){
    unsigned long long r;
    asm("mov.b64 %0, {%1,%2};" : "=l"(r) : "f"(x), "f"(y));
    return r;
}
DINL void unpack2(unsigned long long v, float& x, float& y){
    asm("mov.b64 {%0,%1}, %2;" : "=f"(x), "=f"(y) : "l"(v));
}
DINL void fma2(unsigned long long& d, unsigned long long a, unsigned long long b){
    asm("fma.rn.f32x2 %0, %1, %2, %0;" : "+l"(d) : "l"(a), "l"(b));
}
DINL float sigm(float x){ return 1.0f / (1.0f + expf(-x)); }
DINL float tanh_fast(float x){
    float y;
    asm("tanh.approx.f32 %0, %1;" : "=f"(y) : "f"(x));
    return y;
}

// ---------- sizes ----------
#define B_   8
#define S_   32
#define P_   5
#define C_   528
#define H_   784
#define M_   128
#define NSP  196
#define TOT  1280
#define BSN  256
#define OUTW 1697

// ---------- device scratch ----------
__device__ __align__(16) float g_GI[BSN * 3 * H_];
__device__ __align__(16) float g_h[2][B_ * H_];
__device__ __align__(16) float g_pref[BSN * H_];
__device__ __align__(16) float g_mot[BSN * M_];
__device__ __align__(16) float g_Wt[C_ * M_];
__device__ __align__(16) float g_vidpre[(size_t)TOT * 784];
__device__ __align__(16) float g_bnPart[TOT * 8];
__device__ __align__(16) float g_mstats[2 * M_];
__device__ __align__(16) float g_vstats[8];
__device__ unsigned g_bar;

// ---------- prep: transpose Wv_w [128,528] -> g_Wt [528,128]; reset barrier ----------
__global__ void k_prep(const float* __restrict__ Wv_w){
    int i = blockIdx.x * 256 + threadIdx.x;
    if (i < C_ * M_){
        int m = i / C_, c = i % C_;
        g_Wt[c * M_ + m] = Wv_w[i];
    }
    if (i == 0) g_bar = 0u;
}

// ---------- generic NT GEMM, double-buffered ----------
// C[i,j] = sum_k A[i,k]*B[j,k] (+bias[j]); next k-chunk prefetched into
// registers during compute so the L2/DRAM latency overlaps the FFMA work.
__global__ void k_gemm_nt(const float* __restrict__ Aext, const float* __restrict__ Bm,
                          const float* __restrict__ bias, int atag, int ctag,
                          int M, int N, int K){
    const float* A = (atag == 0) ? Aext : g_pref;
    float* C = (ctag == 0) ? g_GI : g_mot;
    __shared__ float As[32][33];
    __shared__ float Bs[64][33];
    int i0 = blockIdx.y * 32, j0 = blockIdx.x * 64;
    int tid = threadIdx.x;
    int ti = tid >> 4, tj = tid & 15;

    // per-thread fixed (row,col) slots for the staging tiles
    int ar[4], ac[4], br[8], bc[8];
    #pragma unroll
    for (int r = 0; r < 4; r++){ int idx = tid + r * 256; ar[r] = idx >> 5; ac[r] = idx & 31; }
    #pragma unroll
    for (int r = 0; r < 8; r++){ int idx = tid + r * 256; br[r] = idx >> 5; bc[r] = idx & 31; }

    float a_reg[4], b_reg[8];
    // prefetch chunk 0
    #pragma unroll
    for (int r = 0; r < 4; r++){
        float v = 0.0f;
        if (i0 + ar[r] < M && ac[r] < K) v = A[(size_t)(i0 + ar[r]) * K + ac[r]];
        a_reg[r] = v;
    }
    #pragma unroll
    for (int r = 0; r < 8; r++){
        float v = 0.0f;
        if (j0 + br[r] < N && bc[r] < K) v = Bm[(size_t)(j0 + br[r]) * K + bc[r]];
        b_reg[r] = v;
    }

    float acc[2][4] = {{0,0,0,0},{0,0,0,0}};
    for (int k0 = 0; k0 < K; k0 += 32){
        #pragma unroll
        for (int r = 0; r < 4; r++) As[ar[r]][ac[r]] = a_reg[r];
        #pragma unroll
        for (int r = 0; r < 8; r++) Bs[br[r]][bc[r]] = b_reg[r];
        __syncthreads();

        int kn = k0 + 32;
        if (kn < K){
            #pragma unroll
            for (int r = 0; r < 4; r++){
                float v = 0.0f;
                if (i0 + ar[r] < M && kn + ac[r] < K) v = A[(size_t)(i0 + ar[r]) * K + kn + ac[r]];
                a_reg[r] = v;
            }
            #pragma unroll
            for (int r = 0; r < 8; r++){
                float v = 0.0f;
                if (j0 + br[r] < N && kn + bc[r] < K) v = Bm[(size_t)(j0 + br[r]) * K + kn + bc[r]];
                b_reg[r] = v;
            }
        }

        #pragma unroll
        for (int kk = 0; kk < 32; kk++){
            float a0 = As[ti*2][kk], a1 = As[ti*2+1][kk];
            float b0 = Bs[tj*4][kk], b1 = Bs[tj*4+1][kk];
            float b2 = Bs[tj*4+2][kk], b3 = Bs[tj*4+3][kk];
            acc[0][0] += a0*b0; acc[0][1] += a0*b1; acc[0][2] += a0*b2; acc[0][3] += a0*b3;
            acc[1][0] += a1*b0; acc[1][1] += a1*b1; acc[1][2] += a1*b2; acc[1][3] += a1*b3;
        }
        __syncthreads();
    }
    #pragma unroll
    for (int r = 0; r < 2; r++)
        #pragma unroll
        for (int c = 0; c < 4; c++){
            int i = i0 + ti*2 + r, j = j0 + tj*4 + c;
            if (i < M && j < N){
                float v = acc[r][c];
                if (bias) v += bias[j];
                C[(size_t)i * N + j] = v;
            }
        }
}

// ---------- persistent GRU (R9, unchanged) ----------
#define GRU_NCTA 112
#define GRU_THREADS 672
#define GRU_JPC 7
__global__ void __launch_bounds__(GRU_THREADS)
k_gru_all(const float* __restrict__ Whh, const float* __restrict__ bhh){
    __shared__ __align__(16) float4 hs4[B_ * (H_ / 4)];
    __shared__ float gsum[GRU_JPC][3][B_];
    int tid = threadIdx.x, wid = tid >> 5, lane = tid & 31;
    int jj = wid / 3, g = wid % 3;
    int j = blockIdx.x * GRU_JPC + jj;
    const float4* w = reinterpret_cast<const float4*>(Whh + (size_t)(g * H_ + j) * H_);
    float bj[3];
    if (tid < GRU_JPC * B_){
        int j2 = blockIdx.x * GRU_JPC + tid / B_;
        bj[0] = bhh[j2]; bj[1] = bhh[H_ + j2]; bj[2] = bhh[2 * H_ + j2];
    }

    for (int s = 0; s < S_; s++){
        const float* hin = g_h[s & 1];
        float* hout = g_h[(s + 1) & 1];

        if (s > 0){
            const float4* src = reinterpret_cast<const float4*>(hin);
            for (int i = tid; i < B_ * (H_ / 4); i += GRU_THREADS) hs4[i] = src[i];
        }
        __syncthreads();

        float red[B_];
        #pragma unroll
        for (int b = 0; b < B_; b++) red[b] = 0.0f;

        if (s > 0){
            float4 wv[7];
            #pragma unroll
            for (int it = 0; it < 7; it++){
                int k4 = lane + it * 32;
                if (it < 6 || lane < 4) wv[it] = w[k4];
                else                    wv[it] = make_float4(0.f, 0.f, 0.f, 0.f);
            }
            unsigned long long acc[B_];
            #pragma unroll
            for (int b = 0; b < B_; b++) acc[b] = 0ULL;
            #pragma unroll
            for (int it = 0; it < 7; it++){
                int k4 = lane + it * 32;
                bool ok = (it < 6 || lane < 4);
                unsigned long long wl = pack2(wv[it].x, wv[it].y);
                unsigned long long wh = pack2(wv[it].z, wv[it].w);
                if (ok){
                    #pragma unroll
                    for (int b = 0; b < B_; b++){
                        float4 h4 = hs4[b * (H_ / 4) + k4];
                        fma2(acc[b], wl, pack2(h4.x, h4.y));
                        fma2(acc[b], wh, pack2(h4.z, h4.w));
                    }
                }
            }
            #pragma unroll
            for (int b = 0; b < B_; b++){
                float x, y; unpack2(acc[b], x, y);
                red[b] = x + y;
            }
            #pragma unroll
            for (int o = 16; o; o >>= 1)
                #pragma unroll
                for (int b = 0; b < B_; b++)
                    red[b] += __shfl_down_sync(0xffffffffu, red[b], o);
        }
        if (lane == 0){
            #pragma unroll
            for (int b = 0; b < B_; b++) gsum[jj][g][b] = red[b];
        }
        __syncthreads();

        if (tid < GRU_JPC * B_){
            int jj2 = tid / B_, b = tid % B_;
            int j2 = blockIdx.x * GRU_JPC + jj2;
            int bs = b * S_ + s;
            const float* gi = g_GI + (size_t)bs * (3 * H_);
            const float* hsf = reinterpret_cast<const float*>(hs4);
            float r = sigm(gi[j2] + gsum[jj2][0][b] + bj[0]);
            float z = sigm(gi[H_ + j2] + gsum[jj2][1][b] + bj[1]);
            float n = tanhf(gi[2 * H_ + j2] + r * (gsum[jj2][2][b] + bj[2]));
            float hold = (s > 0) ? hsf[b * H_ + j2] : 0.0f;
            float hn = (1.0f - z) * n + z * hold;
            hout[b * H_ + j2] = hn;
            g_pref[(size_t)bs * H_ + j2] = hn;
        }

        __threadfence();
        __syncthreads();
        if (tid == 0){
            atomicAdd(&g_bar, 1u);
            unsigned target = (unsigned)GRU_NCTA * (unsigned)(s + 1);
            while (*((volatile unsigned*)&g_bar) < target) { }
        }
        __syncthreads();
        __threadfence();
    }
}

// ---------- fused attention + p_att + softmax + 1x1 conv; one CTA per t ----------
#define ATT_THREADS 448
#define NCC 8
__global__ void __launch_bounds__(ATT_THREADS, 1)
k_att(const float* __restrict__ video, const float* __restrict__ Wp,
      const float* __restrict__ Wv_b, const float* __restrict__ Wpv,
      const float* __restrict__ conv_w, const float* __restrict__ conv_b){
    __shared__ float Vs[2][NCC * NSP];
    __shared__ __align__(16) float Ws[2][NCC * M_];
    __shared__ float pa_s[M_];
    __shared__ float sc[NSP];
    __shared__ float attb[NSP];
    __shared__ float cw[4 * C_];
    __shared__ float wS[14][8];

    int t = blockIdx.x;
    int bs = t / P_;
    const float* V = video + (size_t)t * (C_ * NSP);
    int tid = threadIdx.x;
    int tj = tid & 15, ti = tid >> 4;
    int m0 = tj * 8, n0 = ti * 7;

    for (int i = tid; i < 4 * C_; i += ATT_THREADS) cw[i] = conv_w[i];

    int wst[3];
    #pragma unroll
    for (int r = 0; r < 3; r++){
        int idx = tid + r * ATT_THREADS;
        if (idx < NCC * M_){
            int cc = idx >> 7, m = idx & 127;
            int p = m >> 1;
            int q = ((p & 3) << 4) | (p >> 2);
            wst[r] = cc * M_ + q * 2 + (m & 1);
        } else wst[r] = -1;
    }

    #pragma unroll
    for (int r = 0; r < 4; r++){
        int idx = tid + r * ATT_THREADS;
        if (idx < NCC * NSP) Vs[0][idx] = V[idx];
    }
    #pragma unroll
    for (int r = 0; r < 3; r++)
        if (wst[r] >= 0) Ws[0][wst[r]] = g_Wt[tid + r * ATT_THREADS];

    // ---- fused p_att: pa_s[m] = dot(pref[bs], Wp[m]) over 784 (L2-resident) ----
    if (tid < M_){
        const float4* pr = reinterpret_cast<const float4*>(g_pref + (size_t)bs * H_);
        const float4* wr = reinterpret_cast<const float4*>(Wp + (size_t)tid * H_);
        float a0 = 0.f, a1 = 0.f, a2 = 0.f, a3 = 0.f;
        #pragma unroll 4
        for (int k = 0; k < H_ / 4; k++){
            float4 p4 = pr[k], w4 = wr[k];
            a0 += p4.x * w4.x; a1 += p4.y * w4.y;
            a2 += p4.z * w4.z; a3 += p4.w * w4.w;
        }
        pa_s[tid] = (a0 + a1) + (a2 + a3);
    }
    __syncthreads();

    unsigned long long acc[7][4];
    #pragma unroll
    for (int i = 0; i < 7; i++)
        #pragma unroll
        for (int j = 0; j < 4; j++) acc[i][j] = 0ULL;

    const int NSTAGE = C_ / NCC; // 66
    for (int st = 0; st < NSTAGE; st++){
        int cur = st & 1;
        float vtmp[4], wtmp[3];
        bool has = (st + 1 < NSTAGE);
        if (has){
            const float* Vn = V + (st + 1) * (NCC * NSP);
            const float* Wn = g_Wt + (st + 1) * (NCC * M_);
            #pragma unroll
            for (int r = 0; r < 4; r++){
                int idx = tid + r * ATT_THREADS;
                vtmp[r] = (idx < NCC * NSP) ? Vn[idx] : 0.0f;
            }
            #pragma unroll
            for (int r = 0; r < 3; r++)
                wtmp[r] = (wst[r] >= 0) ? Wn[tid + r * ATT_THREADS] : 0.0f;
        }
        const float* vsc = Vs[cur];
        const unsigned long long* wsc = reinterpret_cast<const unsigned long long*>(Ws[cur]);
        #pragma unroll
        for (int cc = 0; cc < NCC; cc++){
            unsigned long long bv[4];
            #pragma unroll
            for (int j = 0; j < 4; j++) bv[j] = wsc[cc * 64 + j * 16 + tj];
            #pragma unroll
            for (int i = 0; i < 7; i++){
                float a = vsc[cc * NSP + n0 + i];
                unsigned long long av = pack2(a, a);
                #pragma unroll
                for (int j = 0; j < 4; j++) fma2(acc[i][j], av, bv[j]);
            }
        }
        if (has){
            float* vd = Vs[cur ^ 1];
            float* wd = Ws[cur ^ 1];
            #pragma unroll
            for (int r = 0; r < 4; r++){
                int idx = tid + r * ATT_THREADS;
                if (idx < NCC * NSP) vd[idx] = vtmp[r];
            }
            #pragma unroll
            for (int r = 0; r < 3; r++)
                if (wst[r] >= 0) wd[wst[r]] = wtmp[r];
        }
        __syncthreads();
    }

    float sp[7] = {0,0,0,0,0,0,0};
    #pragma unroll
    for (int j = 0; j < 4; j++){
        int m = m0 + 2 * j;
        float2 pv = *reinterpret_cast<const float2*>(pa_s + m);
        float2 bb = *reinterpret_cast<const float2*>(Wv_b + m);
        float2 ww = *reinterpret_cast<const float2*>(Wpv + m);
        #pragma unroll
        for (int i = 0; i < 7; i++){
            float x, y; unpack2(acc[i][j], x, y);
            x = tanh_fast(x + pv.x + bb.x);
            y = tanh_fast(y + pv.y + bb.y);
            sp[i] += x * ww.x + y * ww.y;
        }
    }
    #pragma unroll
    for (int o = 8; o >= 1; o >>= 1)
        #pragma unroll
        for (int i = 0; i < 7; i++)
            sp[i] += __shfl_xor_sync(0xffffffffu, sp[i], o);
    if (tj == 0){
        #pragma unroll
        for (int i = 0; i < 7; i++) sc[n0 + i] = sp[i];
    }
    __syncthreads();

    if (tid < 32){
        float mx = -3.4e38f;
        for (int n = tid; n < NSP; n += 32) mx = fmaxf(mx, sc[n]);
        #pragma unroll
        for (int o = 16; o; o >>= 1) mx = fmaxf(mx, __shfl_xor_sync(0xffffffffu, mx, o));
        float sm = 0.0f;
        for (int n = tid; n < NSP; n += 32){ float e = expf(sc[n] - mx); attb[n] = e; sm += e; }
        #pragma unroll
        for (int o = 16; o; o >>= 1) sm += __shfl_xor_sync(0xffffffffu, sm, o);
        float inv = 1.0f / sm;
        for (int n = tid; n < NSP; n += 32) attb[n] *= inv;
    }
    __syncthreads();

    float d0 = 0.f, d1 = 0.f, d2 = 0.f, d3 = 0.f;
    int n = tid >> 1, half = tid & 1;
    if (tid < 392){
        const float4* fp = reinterpret_cast<const float4*>(V + (size_t)n * C_ + half * 264);
        #pragma unroll 4
        for (int q = 0; q < 66; q++){
            float4 v4 = fp[q];
            int c = half * 264 + q * 4;
            d0 += v4.x*cw[c]       + v4.y*cw[c+1]       + v4.z*cw[c+2]       + v4.w*cw[c+3];
            d1 += v4.x*cw[528+c]   + v4.y*cw[528+c+1]   + v4.z*cw[528+c+2]   + v4.w*cw[528+c+3];
            d2 += v4.x*cw[1056+c]  + v4.y*cw[1056+c+1]  + v4.z*cw[1056+c+2]  + v4.w*cw[1056+c+3];
            d3 += v4.x*cw[1584+c]  + v4.y*cw[1584+c+1]  + v4.z*cw[1584+c+2]  + v4.w*cw[1584+c+3];
        }
    }
    d0 += __shfl_xor_sync(0xffffffffu, d0, 1);
    d1 += __shfl_xor_sync(0xffffffffu, d1, 1);
    d2 += __shfl_xor_sync(0xffffffffu, d2, 1);
    d3 += __shfl_xor_sync(0xffffffffu, d3, 1);

    float dsum[4] = {0,0,0,0}, dsq[4] = {0,0,0,0};
    if (tid < 392 && half == 0){
        float an = attb[n];
        float vv[4];
        vv[0] = an * d0 + conv_b[0];
        vv[1] = an * d1 + conv_b[1];
        vv[2] = an * d2 + conv_b[2];
        vv[3] = an * d3 + conv_b[3];
        #pragma unroll
        for (int o = 0; o < 4; o++){
            g_vidpre[(size_t)t * 784 + o * NSP + n] = vv[o];
            dsum[o] = vv[o];
            dsq[o] = vv[o] * vv[o];
        }
    }
    #pragma unroll
    for (int o = 0; o < 4; o++){
        #pragma unroll
        for (int sh = 16; sh; sh >>= 1){
            dsum[o] += __shfl_down_sync(0xffffffffu, dsum[o], sh);
            dsq[o]  += __shfl_down_sync(0xffffffffu, dsq[o], sh);
        }
    }
    int wid = tid >> 5, lane = tid & 31;
    if (lane == 0){
        #pragma unroll
        for (int o = 0; o < 4; o++){ wS[wid][o] = dsum[o]; wS[wid][4 + o] = dsq[o]; }
    }
    __syncthreads();
    if (tid < 8){
        float a = 0.f;
        #pragma unroll
        for (int w = 0; w < 14; w++) a += wS[w][tid];
        g_bnPart[t * 8 + tid] = a;
    }
}

// ---------- motion BN stats over 256 rows ----------
__global__ void k_mstats(){
    int m = threadIdx.x;
    float sum = 0.f, sq = 0.f;
    for (int r = 0; r < BSN; r++){
        float v = g_mot[r * M_ + m];
        sum += v; sq += v * v;
    }
    float mu = sum / (float)BSN;
    float var = sq / (float)BSN - mu * mu;
    g_mstats[m] = mu;
    g_mstats[M_ + m] = rsqrtf(var + 1e-5f);
}

// ---------- video BN stats reduce ----------
__global__ void k_vstats(){
    __shared__ float red[256];
    __shared__ float tot[8];
    int tid = threadIdx.x;
    float part[8] = {0,0,0,0,0,0,0,0};
    for (int t = tid; t < TOT; t += 256)
        #pragma unroll
        for (int k = 0; k < 8; k++) part[k] += g_bnPart[t * 8 + k];
    for (int k = 0; k < 8; k++){
        red[tid] = part[k];
        __syncthreads();
        for (int o = 128; o; o >>= 1){
            if (tid < o) red[tid] += red[tid + o];
            __syncthreads();
        }
        if (tid == 0) tot[k] = red[0];
        __syncthreads();
    }
    if (tid < 4){
        float cnt = (float)TOT * (float)NSP;
        float mu = tot[tid] / cnt;
        float var = tot[4 + tid] / cnt - mu * mu;
        g_vstats[tid] = mu;
        g_vstats[4 + tid] = rsqrtf(var + 1e-5f);
    }
}

// ---------- final assembly ----------
__global__ void k_final(const float* __restrict__ tw,
                        const float* __restrict__ vbn_g, const float* __restrict__ vbn_b,
                        const float* __restrict__ mbn_g, const float* __restrict__ mbn_b,
                        float* __restrict__ out){
    int t = blockIdx.x, bs = t / P_, p = t % P_;
    float* o = out + (size_t)t * OUTW;
    for (int c = threadIdx.x; c < OUTW; c += 256){
        float v;
        if (c == 0) v = tw[p];
        else if (c < 785) v = g_pref[(size_t)bs * H_ + (c - 1)];
        else if (c < 913){
            int m = c - 785;
            float x = g_mot[bs * M_ + m];
            v = fmaxf((x - g_mstats[m]) * g_mstats[M_ + m] * mbn_g[m] + mbn_b[m], 0.f);
        } else {
            int idx = c - 913, ch = idx / NSP;
            float x = g_vidpre[(size_t)t * 784 + idx];
            v = fmaxf((x - g_vstats[ch]) * g_vstats[4 + ch] * vbn_g[ch] + vbn_b[ch], 0.f);
        }
        o[c] = v;
    }
}

// ---------- launcher ----------
extern "C" void kernel_launch(void* const* d_in, const int* in_sizes, int n_in,
                              void* d_out, int out_size){
    const float* fov      = (const float*)d_in[0];
    const float* motion   = (const float*)d_in[1];
    const float* video    = (const float*)d_in[2];
    const float* timew    = (const float*)d_in[3];
    const float* gru_w_ih = (const float*)d_in[4];
    const float* gru_w_hh = (const float*)d_in[5];
    const float* gru_b_ih = (const float*)d_in[6];
    const float* gru_b_hh = (const float*)d_in[7];
    const float* Wp       = (const float*)d_in[8];
    const float* Wv_w     = (const float*)d_in[9];
    const float* Wv_b     = (const float*)d_in[10];
    const float* Wpv_w    = (const float*)d_in[11];
    const float* conv_w   = (const float*)d_in[13];
    const float* conv_b   = (const float*)d_in[14];
    const float* vbn_g    = (const float*)d_in[15];
    const float* vbn_b    = (const float*)d_in[16];
    const float* me_w     = (const float*)d_in[17];
    const float* me_b     = (const float*)d_in[18];
    const float* mbn_g    = (const float*)d_in[19];
    const float* mbn_b    = (const float*)d_in[20];
    float* out = (float*)d_out;

    k_prep<<<264, 256>>>(Wv_w);                                           // 1
    k_gemm_nt<<<dim3(37, 8), 256>>>(fov, gru_w_ih, gru_b_ih, 0, 0,
                                    BSN, 3 * H_, C_);                     // 2
    k_gru_all<<<GRU_NCTA, GRU_THREADS>>>(gru_w_hh, gru_b_hh);             // 3
    k_att<<<TOT, ATT_THREADS>>>(video, Wp, Wv_b, Wpv_w, conv_w, conv_b);  // 4 -> ncu
    k_gemm_nt<<<dim3(2, 8), 256>>>(motion, me_w, me_b, 0, 1,
                                   BSN, M_, 90);                          // 5
    k_mstats<<<1, 128>>>();
    k_vstats<<<1, 256>>>();
    k_final<<<TOT, 256>>>(timew, vbn_g, vbn_b, mbn_g, mbn_b, out);
}

// round 11
// speedup vs baseline: 1.1003x; 1.1003x over previous
#include <cuda_runtime.h>
#include <math.h>
#include <stdint.h>

#define DINL __device__ __forceinline__

// ---------- packed fp32x2 helpers (sm_103a) ----------
DINL unsigned long long pack2(float x, float y){
    unsigned long long r;
    asm("mov.b64 %0, {%1,%2};" : "=l"(r) : "f"(x), "f"(y));
    return r;
}
DINL void unpack2(unsigned long long v, float& x, float& y){
    asm("mov.b64 {%0,%1}, %2;" : "=f"(x), "=f"(y) : "l"(v));
}
DINL void fma2(unsigned long long& d, unsigned long long a, unsigned long long b){
    asm("fma.rn.f32x2 %0, %1, %2, %0;" : "+l"(d) : "l"(a), "l"(b));
}
DINL float sigm(float x){ return 1.0f / (1.0f + expf(-x)); }
DINL float tanh_fast(float x){
    float y;
    asm("tanh.approx.f32 %0, %1;" : "=f"(y) : "f"(x));
    return y;
}

// ---------- sizes ----------
#define B_   8
#define S_   32
#define P_   5
#define C_   528
#define H_   784
#define M_   128
#define NSP  196
#define NSPP 224
#define TOT  1280
#define BSN  256
#define OUTW 1697

// ---------- device scratch ----------
__device__ __align__(16) float g_GI[BSN * 3 * H_];
__device__ __align__(16) float g_h[2][B_ * H_];
__device__ __align__(16) float g_pref[BSN * H_];
__device__ __align__(16) float g_patt[BSN * M_];
__device__ __align__(16) float g_mot[BSN * M_];
__device__ __align__(16) float g_Wt[C_ * M_];
__device__ __align__(16) float g_vidpre[(size_t)TOT * 784];
__device__ __align__(16) float g_bnPart[TOT * 8];
__device__ __align__(16) float g_mstats[2 * M_];
__device__ __align__(16) float g_vstats[8];
__device__ unsigned g_bar;

// ---------- prep: transpose Wv_w [128,528] -> g_Wt [528,128]; reset barrier ----------
__global__ void k_prep(const float* __restrict__ Wv_w){
    int i = blockIdx.x * 256 + threadIdx.x;
    if (i < C_ * M_){
        int m = i / C_, c = i % C_;
        g_Wt[c * M_ + m] = Wv_w[i];
    }
    if (i == 0) g_bar = 0u;
}

// ---------- generic NT GEMM, double-buffered ----------
// C[i,j] = sum_k A[i,k]*B[j,k] (+bias[j]).
// atag: 0 = Aext, 1 = g_pref.  ctag: 0 = g_GI, 1 = g_patt, 2 = g_mot.
__global__ void k_gemm_nt(const float* __restrict__ Aext, const float* __restrict__ Bm,
                          const float* __restrict__ bias, int atag, int ctag,
                          int M, int N, int K){
    const float* A = (atag == 0) ? Aext : g_pref;
    float* C = (ctag == 0) ? g_GI : (ctag == 1 ? g_patt : g_mot);
    __shared__ float As[32][33];
    __shared__ float Bs[64][33];
    int i0 = blockIdx.y * 32, j0 = blockIdx.x * 64;
    int tid = threadIdx.x;
    int ti = tid >> 4, tj = tid & 15;

    int ar[4], ac[4], br[8], bc[8];
    #pragma unroll
    for (int r = 0; r < 4; r++){ int idx = tid + r * 256; ar[r] = idx >> 5; ac[r] = idx & 31; }
    #pragma unroll
    for (int r = 0; r < 8; r++){ int idx = tid + r * 256; br[r] = idx >> 5; bc[r] = idx & 31; }

    float a_reg[4], b_reg[8];
    #pragma unroll
    for (int r = 0; r < 4; r++){
        float v = 0.0f;
        if (i0 + ar[r] < M && ac[r] < K) v = A[(size_t)(i0 + ar[r]) * K + ac[r]];
        a_reg[r] = v;
    }
    #pragma unroll
    for (int r = 0; r < 8; r++){
        float v = 0.0f;
        if (j0 + br[r] < N && bc[r] < K) v = Bm[(size_t)(j0 + br[r]) * K + bc[r]];
        b_reg[r] = v;
    }

    float acc[2][4] = {{0,0,0,0},{0,0,0,0}};
    for (int k0 = 0; k0 < K; k0 += 32){
        #pragma unroll
        for (int r = 0; r < 4; r++) As[ar[r]][ac[r]] = a_reg[r];
        #pragma unroll
        for (int r = 0; r < 8; r++) Bs[br[r]][bc[r]] = b_reg[r];
        __syncthreads();

        int kn = k0 + 32;
        if (kn < K){
            #pragma unroll
            for (int r = 0; r < 4; r++){
                float v = 0.0f;
                if (i0 + ar[r] < M && kn + ac[r] < K) v = A[(size_t)(i0 + ar[r]) * K + kn + ac[r]];
                a_reg[r] = v;
            }
            #pragma unroll
            for (int r = 0; r < 8; r++){
                float v = 0.0f;
                if (j0 + br[r] < N && kn + bc[r] < K) v = Bm[(size_t)(j0 + br[r]) * K + kn + bc[r]];
                b_reg[r] = v;
            }
        }

        #pragma unroll
        for (int kk = 0; kk < 32; kk++){
            float a0 = As[ti*2][kk], a1 = As[ti*2+1][kk];
            float b0 = Bs[tj*4][kk], b1 = Bs[tj*4+1][kk];
            float b2 = Bs[tj*4+2][kk], b3 = Bs[tj*4+3][kk];
            acc[0][0] += a0*b0; acc[0][1] += a0*b1; acc[0][2] += a0*b2; acc[0][3] += a0*b3;
            acc[1][0] += a1*b0; acc[1][1] += a1*b1; acc[1][2] += a1*b2; acc[1][3] += a1*b3;
        }
        __syncthreads();
    }
    #pragma unroll
    for (int r = 0; r < 2; r++)
        #pragma unroll
        for (int c = 0; c < 4; c++){
            int i = i0 + ti*2 + r, j = j0 + tj*4 + c;
            if (i < M && j < N){
                float v = acc[r][c];
                if (bias) v += bias[j];
                C[(size_t)i * N + j] = v;
            }
        }
}

// ---------- persistent GRU (unchanged) ----------
#define GRU_NCTA 112
#define GRU_THREADS 672
#define GRU_JPC 7
__global__ void __launch_bounds__(GRU_THREADS)
k_gru_all(const float* __restrict__ Whh, const float* __restrict__ bhh){
    __shared__ __align__(16) float4 hs4[B_ * (H_ / 4)];
    __shared__ float gsum[GRU_JPC][3][B_];
    int tid = threadIdx.x, wid = tid >> 5, lane = tid & 31;
    int jj = wid / 3, g = wid % 3;
    int j = blockIdx.x * GRU_JPC + jj;
    const float4* w = reinterpret_cast<const float4*>(Whh + (size_t)(g * H_ + j) * H_);
    float bj[3];
    if (tid < GRU_JPC * B_){
        int j2 = blockIdx.x * GRU_JPC + tid / B_;
        bj[0] = bhh[j2]; bj[1] = bhh[H_ + j2]; bj[2] = bhh[2 * H_ + j2];
    }

    for (int s = 0; s < S_; s++){
        const float* hin = g_h[s & 1];
        float* hout = g_h[(s + 1) & 1];

        if (s > 0){
            const float4* src = reinterpret_cast<const float4*>(hin);
            for (int i = tid; i < B_ * (H_ / 4); i += GRU_THREADS) hs4[i] = src[i];
        }
        __syncthreads();

        float red[B_];
        #pragma unroll
        for (int b = 0; b < B_; b++) red[b] = 0.0f;

        if (s > 0){
            float4 wv[7];
            #pragma unroll
            for (int it = 0; it < 7; it++){
                int k4 = lane + it * 32;
                if (it < 6 || lane < 4) wv[it] = w[k4];
                else                    wv[it] = make_float4(0.f, 0.f, 0.f, 0.f);
            }
            unsigned long long acc[B_];
            #pragma unroll
            for (int b = 0; b < B_; b++) acc[b] = 0ULL;
            #pragma unroll
            for (int it = 0; it < 7; it++){
                int k4 = lane + it * 32;
                bool ok = (it < 6 || lane < 4);
                unsigned long long wl = pack2(wv[it].x, wv[it].y);
                unsigned long long wh = pack2(wv[it].z, wv[it].w);
                if (ok){
                    #pragma unroll
                    for (int b = 0; b < B_; b++){
                        float4 h4 = hs4[b * (H_ / 4) + k4];
                        fma2(acc[b], wl, pack2(h4.x, h4.y));
                        fma2(acc[b], wh, pack2(h4.z, h4.w));
                    }
                }
            }
            #pragma unroll
            for (int b = 0; b < B_; b++){
                float x, y; unpack2(acc[b], x, y);
                red[b] = x + y;
            }
            #pragma unroll
            for (int o = 16; o; o >>= 1)
                #pragma unroll
                for (int b = 0; b < B_; b++)
                    red[b] += __shfl_down_sync(0xffffffffu, red[b], o);
        }
        if (lane == 0){
            #pragma unroll
            for (int b = 0; b < B_; b++) gsum[jj][g][b] = red[b];
        }
        __syncthreads();

        if (tid < GRU_JPC * B_){
            int jj2 = tid / B_, b = tid % B_;
            int j2 = blockIdx.x * GRU_JPC + jj2;
            int bs = b * S_ + s;
            const float* gi = g_GI + (size_t)bs * (3 * H_);
            const float* hsf = reinterpret_cast<const float*>(hs4);
            float r = sigm(gi[j2] + gsum[jj2][0][b] + bj[0]);
            float z = sigm(gi[H_ + j2] + gsum[jj2][1][b] + bj[1]);
            float n = tanhf(gi[2 * H_ + j2] + r * (gsum[jj2][2][b] + bj[2]));
            float hold = (s > 0) ? hsf[b * H_ + j2] : 0.0f;
            float hn = (1.0f - z) * n + z * hold;
            hout[b * H_ + j2] = hn;
            g_pref[(size_t)bs * H_ + j2] = hn;
        }

        __threadfence();
        __syncthreads();
        if (tid == 0){
            atomicAdd(&g_bar, 1u);
            unsigned target = (unsigned)GRU_NCTA * (unsigned)(s + 1);
            while (*((volatile unsigned*)&g_bar) < target) { }
        }
        __syncthreads();
        __threadfence();
    }
}

// ---------- fused attention + softmax + 1x1 conv; one CTA per t ----------
// 896 threads (28 warps): thread (ti 0..55, tj 0..15) owns n-tile 4 (padded
// 196->224 so the 4 a-values load as ONE aligned LDS.128 broadcast) x m-tile 8.
#define ATT_THREADS 896
#define NCC 8
__global__ void __launch_bounds__(ATT_THREADS, 1)
k_att(const float* __restrict__ video, const float* __restrict__ Wv_b,
      const float* __restrict__ Wpv, const float* __restrict__ conv_w,
      const float* __restrict__ conv_b){
    __shared__ __align__(16) float Vs[2][NCC * NSPP];
    __shared__ __align__(16) float Ws[2][NCC * M_];
    __shared__ float sc[NSP];
    __shared__ float attb[NSP];
    __shared__ float cw[4 * C_];
    __shared__ float wS[28][8];

    int t = blockIdx.x;
    int bs = t / P_;
    const float* V = video + (size_t)t * (C_ * NSP);
    int tid = threadIdx.x;
    int tj = tid & 15, ti = tid >> 4;     // ti 0..55
    int m0 = tj * 8, n0 = ti * 4;

    for (int i = tid; i < 4 * C_; i += ATT_THREADS) cw[i] = conv_w[i];

    // W permutation (R6-proven): pair p -> slot ((p&3)<<4)|(p>>2)
    int wst[2];
    #pragma unroll
    for (int r = 0; r < 2; r++){
        int idx = tid + r * ATT_THREADS;
        if (idx < NCC * M_){
            int cc = idx >> 7, m = idx & 127;
            int p = m >> 1;
            int q = ((p & 3) << 4) | (p >> 2);
            wst[r] = cc * M_ + q * 2 + (m & 1);
        } else wst[r] = -1;
    }

    // prologue stage 0 (V padded: cols >=196 are zero)
    #pragma unroll
    for (int r = 0; r < 2; r++){
        int idx = tid + r * ATT_THREADS;           // < 1792 always
        int cc = idx / NSPP, col = idx - cc * NSPP;
        Vs[0][idx] = (col < NSP) ? V[cc * NSP + col] : 0.0f;
    }
    #pragma unroll
    for (int r = 0; r < 2; r++)
        if (wst[r] >= 0) Ws[0][wst[r]] = g_Wt[tid + r * ATT_THREADS];
    __syncthreads();

    unsigned long long acc[4][4];
    #pragma unroll
    for (int i = 0; i < 4; i++)
        #pragma unroll
        for (int j = 0; j < 4; j++) acc[i][j] = 0ULL;

    const int NSTAGE = C_ / NCC; // 66
    for (int st = 0; st < NSTAGE; st++){
        int cur = st & 1;
        float vtmp[2], wtmp[2];
        bool has = (st + 1 < NSTAGE);
        if (has){
            const float* Vn = V + (st + 1) * (NCC * NSP);
            const float* Wn = g_Wt + (st + 1) * (NCC * M_);
            #pragma unroll
            for (int r = 0; r < 2; r++){
                int idx = tid + r * ATT_THREADS;
                int cc = idx / NSPP, col = idx - cc * NSPP;
                vtmp[r] = (col < NSP) ? Vn[cc * NSP + col] : 0.0f;
            }
            #pragma unroll
            for (int r = 0; r < 2; r++)
                wtmp[r] = (wst[r] >= 0) ? Wn[tid + r * ATT_THREADS] : 0.0f;
        }
        const float* vsc = Vs[cur];
        const unsigned long long* wsc = reinterpret_cast<const unsigned long long*>(Ws[cur]);
        #pragma unroll
        for (int cc = 0; cc < NCC; cc++){
            unsigned long long bv[4];
            #pragma unroll
            for (int j = 0; j < 4; j++) bv[j] = wsc[cc * 64 + j * 16 + tj];
            float4 a4 = *reinterpret_cast<const float4*>(vsc + cc * NSPP + n0);
            unsigned long long av0 = pack2(a4.x, a4.x);
            unsigned long long av1 = pack2(a4.y, a4.y);
            unsigned long long av2 = pack2(a4.z, a4.z);
            unsigned long long av3 = pack2(a4.w, a4.w);
            #pragma unroll
            for (int j = 0; j < 4; j++){
                fma2(acc[0][j], av0, bv[j]);
                fma2(acc[1][j], av1, bv[j]);
                fma2(acc[2][j], av2, bv[j]);
                fma2(acc[3][j], av3, bv[j]);
            }
        }
        if (has){
            float* vd = Vs[cur ^ 1];
            float* wd = Ws[cur ^ 1];
            #pragma unroll
            for (int r = 0; r < 2; r++){
                int idx = tid + r * ATT_THREADS;
                vd[idx] = vtmp[r];
            }
            #pragma unroll
            for (int r = 0; r < 2; r++)
                if (wst[r] >= 0) wd[wst[r]] = wtmp[r];
        }
        __syncthreads();
    }

    // epilogue: tanh(raw + p_att + Wv_b) dot Wpv -> scores (rows n0..n0+3)
    const float* pa = g_patt + (size_t)bs * M_;
    float sp[4] = {0,0,0,0};
    #pragma unroll
    for (int j = 0; j < 4; j++){
        int m = m0 + 2 * j;
        float2 pv = *reinterpret_cast<const float2*>(pa + m);
        float2 bb = *reinterpret_cast<const float2*>(Wv_b + m);
        float2 ww = *reinterpret_cast<const float2*>(Wpv + m);
        #pragma unroll
        for (int i = 0; i < 4; i++){
            float x, y; unpack2(acc[i][j], x, y);
            x = tanh_fast(x + pv.x + bb.x);
            y = tanh_fast(y + pv.y + bb.y);
            sp[i] += x * ww.x + y * ww.y;
        }
    }
    #pragma unroll
    for (int o = 8; o >= 1; o >>= 1)
        #pragma unroll
        for (int i = 0; i < 4; i++)
            sp[i] += __shfl_xor_sync(0xffffffffu, sp[i], o);
    if (tj == 0 && n0 < NSP){
        #pragma unroll
        for (int i = 0; i < 4; i++) sc[n0 + i] = sp[i];
    }
    __syncthreads();

    if (tid < 32){
        float mx = -3.4e38f;
        for (int n = tid; n < NSP; n += 32) mx = fmaxf(mx, sc[n]);
        #pragma unroll
        for (int o = 16; o; o >>= 1) mx = fmaxf(mx, __shfl_xor_sync(0xffffffffu, mx, o));
        float sm = 0.0f;
        for (int n = tid; n < NSP; n += 32){ float e = expf(sc[n] - mx); attb[n] = e; sm += e; }
        #pragma unroll
        for (int o = 16; o; o >>= 1) sm += __shfl_xor_sync(0xffffffffu, sm, o);
        float inv = 1.0f / sm;
        for (int n = tid; n < NSP; n += 32) attb[n] *= inv;
    }
    __syncthreads();

    float d0 = 0.f, d1 = 0.f, d2 = 0.f, d3 = 0.f;
    int n = tid >> 1, half = tid & 1;
    if (tid < 392){
        const float4* fp = reinterpret_cast<const float4*>(V + (size_t)n * C_ + half * 264);
        #pragma unroll 4
        for (int q = 0; q < 66; q++){
            float4 v4 = fp[q];
            int c = half * 264 + q * 4;
            d0 += v4.x*cw[c]       + v4.y*cw[c+1]       + v4.z*cw[c+2]       + v4.w*cw[c+3];
            d1 += v4.x*cw[528+c]   + v4.y*cw[528+c+1]   + v4.z*cw[528+c+2]   + v4.w*cw[528+c+3];
            d2 += v4.x*cw[1056+c]  + v4.y*cw[1056+c+1]  + v4.z*cw[1056+c+2]  + v4.w*cw[1056+c+3];
            d3 += v4.x*cw[1584+c]  + v4.y*cw[1584+c+1]  + v4.z*cw[1584+c+2]  + v4.w*cw[1584+c+3];
        }
    }
    d0 += __shfl_xor_sync(0xffffffffu, d0, 1);
    d1 += __shfl_xor_sync(0xffffffffu, d1, 1);
    d2 += __shfl_xor_sync(0xffffffffu, d2, 1);
    d3 += __shfl_xor_sync(0xffffffffu, d3, 1);

    float dsum[4] = {0,0,0,0}, dsq[4] = {0,0,0,0};
    if (tid < 392 && half == 0){
        float an = attb[n];
        float vv[4];
        vv[0] = an * d0 + conv_b[0];
        vv[1] = an * d1 + conv_b[1];
        vv[2] = an * d2 + conv_b[2];
        vv[3] = an * d3 + conv_b[3];
        #pragma unroll
        for (int o = 0; o < 4; o++){
            g_vidpre[(size_t)t * 784 + o * NSP + n] = vv[o];
            dsum[o] = vv[o];
            dsq[o] = vv[o] * vv[o];
        }
    }
    #pragma unroll
    for (int o = 0; o < 4; o++){
        #pragma unroll
        for (int sh = 16; sh; sh >>= 1){
            dsum[o] += __shfl_down_sync(0xffffffffu, dsum[o], sh);
            dsq[o]  += __shfl_down_sync(0xffffffffu, dsq[o], sh);
        }
    }
    int wid = tid >> 5, lane = tid & 31;
    if (lane == 0){
        #pragma unroll
        for (int o = 0; o < 4; o++){ wS[wid][o] = dsum[o]; wS[wid][4 + o] = dsq[o]; }
    }
    __syncthreads();
    if (tid < 8){
        float a = 0.f;
        #pragma unroll
        for (int w = 0; w < 28; w++) a += wS[w][tid];
        g_bnPart[t * 8 + tid] = a;
    }
}

// ---------- motion BN stats over 256 rows ----------
__global__ void k_mstats(){
    int m = threadIdx.x;
    float sum = 0.f, sq = 0.f;
    for (int r = 0; r < BSN; r++){
        float v = g_mot[r * M_ + m];
        sum += v; sq += v * v;
    }
    float mu = sum / (float)BSN;
    float var = sq / (float)BSN - mu * mu;
    g_mstats[m] = mu;
    g_mstats[M_ + m] = rsqrtf(var + 1e-5f);
}

// ---------- video BN stats reduce ----------
__global__ void k_vstats(){
    __shared__ float red[256];
    __shared__ float tot[8];
    int tid = threadIdx.x;
    float part[8] = {0,0,0,0,0,0,0,0};
    for (int t = tid; t < TOT; t += 256)
        #pragma unroll
        for (int k = 0; k < 8; k++) part[k] += g_bnPart[t * 8 + k];
    for (int k = 0; k < 8; k++){
        red[tid] = part[k];
        __syncthreads();
        for (int o = 128; o; o >>= 1){
            if (tid < o) red[tid] += red[tid + o];
            __syncthreads();
        }
        if (tid == 0) tot[k] = red[0];
        __syncthreads();
    }
    if (tid < 4){
        float cnt = (float)TOT * (float)NSP;
        float mu = tot[tid] / cnt;
        float var = tot[4 + tid] / cnt - mu * mu;
        g_vstats[tid] = mu;
        g_vstats[4 + tid] = rsqrtf(var + 1e-5f);
    }
}

// ---------- final assembly ----------
__global__ void k_final(const float* __restrict__ tw,
                        const float* __restrict__ vbn_g, const float* __restrict__ vbn_b,
                        const float* __restrict__ mbn_g, const float* __restrict__ mbn_b,
                        float* __restrict__ out){
    int t = blockIdx.x, bs = t / P_, p = t % P_;
    float* o = out + (size_t)t * OUTW;
    for (int c = threadIdx.x; c < OUTW; c += 256){
        float v;
        if (c == 0) v = tw[p];
        else if (c < 785) v = g_pref[(size_t)bs * H_ + (c - 1)];
        else if (c < 913){
            int m = c - 785;
            float x = g_mot[bs * M_ + m];
            v = fmaxf((x - g_mstats[m]) * g_mstats[M_ + m] * mbn_g[m] + mbn_b[m], 0.f);
        } else {
            int idx = c - 913, ch = idx / NSP;
            float x = g_vidpre[(size_t)t * 784 + idx];
            v = fmaxf((x - g_vstats[ch]) * g_vstats[4 + ch] * vbn_g[ch] + vbn_b[ch], 0.f);
        }
        o[c] = v;
    }
}

// ---------- launcher ----------
extern "C" void kernel_launch(void* const* d_in, const int* in_sizes, int n_in,
                              void* d_out, int out_size){
    const float* fov      = (const float*)d_in[0];
    const float* motion   = (const float*)d_in[1];
    const float* video    = (const float*)d_in[2];
    const float* timew    = (const float*)d_in[3];
    const float* gru_w_ih = (const float*)d_in[4];
    const float* gru_w_hh = (const float*)d_in[5];
    const float* gru_b_ih = (const float*)d_in[6];
    const float* gru_b_hh = (const float*)d_in[7];
    const float* Wp       = (const float*)d_in[8];
    const float* Wv_w     = (const float*)d_in[9];
    const float* Wv_b     = (const float*)d_in[10];
    const float* Wpv_w    = (const float*)d_in[11];
    const float* conv_w   = (const float*)d_in[13];
    const float* conv_b   = (const float*)d_in[14];
    const float* vbn_g    = (const float*)d_in[15];
    const float* vbn_b    = (const float*)d_in[16];
    const float* me_w     = (const float*)d_in[17];
    const float* me_b     = (const float*)d_in[18];
    const float* mbn_g    = (const float*)d_in[19];
    const float* mbn_b    = (const float*)d_in[20];
    float* out = (float*)d_out;

    k_prep<<<264, 256>>>(Wv_w);                                           // 1
    k_gemm_nt<<<dim3(37, 8), 256>>>(fov, gru_w_ih, gru_b_ih, 0, 0,
                                    BSN, 3 * H_, C_);                     // 2
    k_gru_all<<<GRU_NCTA, GRU_THREADS>>>(gru_w_hh, gru_b_hh);             // 3
    k_gemm_nt<<<dim3(2, 8), 256>>>(nullptr, Wp, nullptr, 1, 1,
                                   BSN, M_, H_);                          // 4 -> ncu (double-buffer check)
    k_att<<<TOT, ATT_THREADS>>>(video, Wv_b, Wpv_w, conv_w, conv_b);      // 5
    k_gemm_nt<<<dim3(2, 8), 256>>>(motion, me_w, me_b, 0, 2,
                                   BSN, M_, 90);                          // 6
    k_mstats<<<1, 128>>>();
    k_vstats<<<1, 256>>>();
    k_final<<<TOT, 256>>>(timew, vbn_g, vbn_b, mbn_g, mbn_b, out);
}

// round 12
// speedup vs baseline: 1.1059x; 1.0050x over previous
#include <cuda_runtime.h>
#include <math.h>
#include <stdint.h>

#define DINL __device__ __forceinline__

// ---------- packed fp32x2 helpers (sm_103a) ----------
DINL unsigned long long pack2(float x, float y){
    unsigned long long r;
    asm("mov.b64 %0, {%1,%2};" : "=l"(r) : "f"(x), "f"(y));
    return r;
}
DINL void unpack2(unsigned long long v, float& x, float& y){
    asm("mov.b64 {%0,%1}, %2;" : "=f"(x), "=f"(y) : "l"(v));
}
DINL void fma2(unsigned long long& d, unsigned long long a, unsigned long long b){
    asm("fma.rn.f32x2 %0, %1, %2, %0;" : "+l"(d) : "l"(a), "l"(b));
}
DINL float sigm(float x){ return 1.0f / (1.0f + expf(-x)); }
DINL float tanh_fast(float x){
    float y;
    asm("tanh.approx.f32 %0, %1;" : "=f"(y) : "f"(x));
    return y;
}

// ---------- sizes ----------
#define B_   8
#define S_   32
#define P_   5
#define C_   528
#define H_   784
#define M_   128
#define NSP  196
#define NSPP 224
#define TOT  1280
#define BSN  256
#define OUTW 1697

// ---------- device scratch ----------
__device__ __align__(16) float g_GI[BSN * 3 * H_];
__device__ __align__(16) float g_h[2][B_ * H_];
__device__ __align__(16) float g_pref[BSN * H_];
__device__ __align__(16) float g_patt[BSN * M_];
__device__ __align__(16) float g_mot[BSN * M_];
__device__ __align__(16) float g_Wt[C_ * M_];
__device__ __align__(16) float g_vidpre[(size_t)TOT * 784];
__device__ __align__(16) float g_bnPart[TOT * 8];
__device__ __align__(16) float g_mstats[2 * M_];
__device__ __align__(16) float g_vstats[8];
__device__ unsigned g_bar;

// ---------- prep: transpose Wv_w [128,528] -> g_Wt [528,128]; reset barrier ----------
__global__ void k_prep(const float* __restrict__ Wv_w){
    int i = blockIdx.x * 256 + threadIdx.x;
    if (i < C_ * M_){
        int m = i / C_, c = i % C_;
        g_Wt[c * M_ + m] = Wv_w[i];
    }
    if (i == 0) g_bar = 0u;
}

// ---------- generic NT GEMM, double-buffered ----------
// C[i,j] = sum_k A[i,k]*B[j,k] (+bias[j]).  ctag: 0 = g_GI, 2 = g_mot.
__global__ void k_gemm_nt(const float* __restrict__ Aext, const float* __restrict__ Bm,
                          const float* __restrict__ bias, int ctag,
                          int M, int N, int K){
    const float* A = Aext;
    float* C = (ctag == 0) ? g_GI : g_mot;
    __shared__ float As[32][33];
    __shared__ float Bs[64][33];
    int i0 = blockIdx.y * 32, j0 = blockIdx.x * 64;
    int tid = threadIdx.x;
    int ti = tid >> 4, tj = tid & 15;

    int ar[4], ac[4], br[8], bc[8];
    #pragma unroll
    for (int r = 0; r < 4; r++){ int idx = tid + r * 256; ar[r] = idx >> 5; ac[r] = idx & 31; }
    #pragma unroll
    for (int r = 0; r < 8; r++){ int idx = tid + r * 256; br[r] = idx >> 5; bc[r] = idx & 31; }

    float a_reg[4], b_reg[8];
    #pragma unroll
    for (int r = 0; r < 4; r++){
        float v = 0.0f;
        if (i0 + ar[r] < M && ac[r] < K) v = A[(size_t)(i0 + ar[r]) * K + ac[r]];
        a_reg[r] = v;
    }
    #pragma unroll
    for (int r = 0; r < 8; r++){
        float v = 0.0f;
        if (j0 + br[r] < N && bc[r] < K) v = Bm[(size_t)(j0 + br[r]) * K + bc[r]];
        b_reg[r] = v;
    }

    float acc[2][4] = {{0,0,0,0},{0,0,0,0}};
    for (int k0 = 0; k0 < K; k0 += 32){
        #pragma unroll
        for (int r = 0; r < 4; r++) As[ar[r]][ac[r]] = a_reg[r];
        #pragma unroll
        for (int r = 0; r < 8; r++) Bs[br[r]][bc[r]] = b_reg[r];
        __syncthreads();

        int kn = k0 + 32;
        if (kn < K){
            #pragma unroll
            for (int r = 0; r < 4; r++){
                float v = 0.0f;
                if (i0 + ar[r] < M && kn + ac[r] < K) v = A[(size_t)(i0 + ar[r]) * K + kn + ac[r]];
                a_reg[r] = v;
            }
            #pragma unroll
            for (int r = 0; r < 8; r++){
                float v = 0.0f;
                if (j0 + br[r] < N && kn + bc[r] < K) v = Bm[(size_t)(j0 + br[r]) * K + kn + bc[r]];
                b_reg[r] = v;
            }
        }

        #pragma unroll
        for (int kk = 0; kk < 32; kk++){
            float a0 = As[ti*2][kk], a1 = As[ti*2+1][kk];
            float b0 = Bs[tj*4][kk], b1 = Bs[tj*4+1][kk];
            float b2 = Bs[tj*4+2][kk], b3 = Bs[tj*4+3][kk];
            acc[0][0] += a0*b0; acc[0][1] += a0*b1; acc[0][2] += a0*b2; acc[0][3] += a0*b3;
            acc[1][0] += a1*b0; acc[1][1] += a1*b1; acc[1][2] += a1*b2; acc[1][3] += a1*b3;
        }
        __syncthreads();
    }
    #pragma unroll
    for (int r = 0; r < 2; r++)
        #pragma unroll
        for (int c = 0; c < 4; c++){
            int i = i0 + ti*2 + r, j = j0 + tj*4 + c;
            if (i < M && j < N){
                float v = acc[r][c];
                if (bias) v += bias[j];
                C[(size_t)i * N + j] = v;
            }
        }
}

// ---------- persistent GRU + fused p_att tail ----------
#define GRU_NCTA 112
#define GRU_THREADS 672
#define GRU_JPC 7
__global__ void __launch_bounds__(GRU_THREADS)
k_gru_all(const float* __restrict__ Whh, const float* __restrict__ bhh,
          const float* __restrict__ Wp){
    __shared__ __align__(16) float4 hs4[B_ * (H_ / 4)];
    __shared__ float gsum[GRU_JPC][3][B_];
    int tid = threadIdx.x, wid = tid >> 5, lane = tid & 31;
    int jj = wid / 3, g = wid % 3;
    int j = blockIdx.x * GRU_JPC + jj;
    const float4* w = reinterpret_cast<const float4*>(Whh + (size_t)(g * H_ + j) * H_);
    float bj[3];
    if (tid < GRU_JPC * B_){
        int j2 = blockIdx.x * GRU_JPC + tid / B_;
        bj[0] = bhh[j2]; bj[1] = bhh[H_ + j2]; bj[2] = bhh[2 * H_ + j2];
    }

    for (int s = 0; s < S_; s++){
        const float* hin = g_h[s & 1];
        float* hout = g_h[(s + 1) & 1];

        if (s > 0){
            const float4* src = reinterpret_cast<const float4*>(hin);
            for (int i = tid; i < B_ * (H_ / 4); i += GRU_THREADS) hs4[i] = src[i];
        }
        __syncthreads();

        float red[B_];
        #pragma unroll
        for (int b = 0; b < B_; b++) red[b] = 0.0f;

        if (s > 0){
            float4 wv[7];
            #pragma unroll
            for (int it = 0; it < 7; it++){
                int k4 = lane + it * 32;
                if (it < 6 || lane < 4) wv[it] = w[k4];
                else                    wv[it] = make_float4(0.f, 0.f, 0.f, 0.f);
            }
            unsigned long long acc[B_];
            #pragma unroll
            for (int b = 0; b < B_; b++) acc[b] = 0ULL;
            #pragma unroll
            for (int it = 0; it < 7; it++){
                int k4 = lane + it * 32;
                bool ok = (it < 6 || lane < 4);
                unsigned long long wl = pack2(wv[it].x, wv[it].y);
                unsigned long long wh = pack2(wv[it].z, wv[it].w);
                if (ok){
                    #pragma unroll
                    for (int b = 0; b < B_; b++){
                        float4 h4 = hs4[b * (H_ / 4) + k4];
                        fma2(acc[b], wl, pack2(h4.x, h4.y));
                        fma2(acc[b], wh, pack2(h4.z, h4.w));
                    }
                }
            }
            #pragma unroll
            for (int b = 0; b < B_; b++){
                float x, y; unpack2(acc[b], x, y);
                red[b] = x + y;
            }
            #pragma unroll
            for (int o = 16; o; o >>= 1)
                #pragma unroll
                for (int b = 0; b < B_; b++)
                    red[b] += __shfl_down_sync(0xffffffffu, red[b], o);
        }
        if (lane == 0){
            #pragma unroll
            for (int b = 0; b < B_; b++) gsum[jj][g][b] = red[b];
        }
        __syncthreads();

        if (tid < GRU_JPC * B_){
            int jj2 = tid / B_, b = tid % B_;
            int j2 = blockIdx.x * GRU_JPC + jj2;
            int bs = b * S_ + s;
            const float* gi = g_GI + (size_t)bs * (3 * H_);
            const float* hsf = reinterpret_cast<const float*>(hs4);
            float r = sigm(gi[j2] + gsum[jj2][0][b] + bj[0]);
            float z = sigm(gi[H_ + j2] + gsum[jj2][1][b] + bj[1]);
            float n = tanhf(gi[2 * H_ + j2] + r * (gsum[jj2][2][b] + bj[2]));
            float hold = (s > 0) ? hsf[b * H_ + j2] : 0.0f;
            float hn = (1.0f - z) * n + z * hold;
            hout[b * H_ + j2] = hn;
            g_pref[(size_t)bs * H_ + j2] = hn;
        }

        __threadfence();
        __syncthreads();
        if (tid == 0){
            atomicAdd(&g_bar, 1u);
            unsigned target = (unsigned)GRU_NCTA * (unsigned)(s + 1);
            while (*((volatile unsigned*)&g_bar) < target) { }
        }
        __syncthreads();
        __threadfence();
    }

    // ---- fused p_att tail: this CTA handles bs rows blockIdx.x, +112, +240 ----
    // All g_pref writes are visible (fence + full grid barrier above).
    float* prow = reinterpret_cast<float*>(hs4);   // reuse smem: up to 3*784 floats
    int bsl[3]; int nbs = 0;
    for (int r = blockIdx.x; r < BSN; r += GRU_NCTA) bsl[nbs++] = r;
    __syncthreads();
    for (int i = tid; i < nbs * H_; i += GRU_THREADS){
        int r = i / H_, k = i - r * H_;
        prow[r * H_ + k] = g_pref[(size_t)bsl[r] * H_ + k];
    }
    __syncthreads();

    for (int m = wid; m < M_; m += (GRU_THREADS / 32)){
        const float4* wr = reinterpret_cast<const float4*>(Wp + (size_t)m * H_);
        float a[3] = {0.f, 0.f, 0.f};
        for (int k4 = lane; k4 < H_ / 4; k4 += 32){
            float4 w4 = wr[k4];
            for (int r = 0; r < nbs; r++){
                float4 p4 = reinterpret_cast<const float4*>(prow + r * H_)[k4];
                a[r] += p4.x * w4.x + p4.y * w4.y + p4.z * w4.z + p4.w * w4.w;
            }
        }
        #pragma unroll
        for (int o = 16; o; o >>= 1)
            for (int r = 0; r < 3; r++)
                a[r] += __shfl_down_sync(0xffffffffu, a[r], o);
        if (lane == 0)
            for (int r = 0; r < nbs; r++)
                g_patt[(size_t)bsl[r] * M_ + m] = a[r];
    }
}

// ---------- fused attention + softmax + 1x1 conv; one CTA per t (R11) ----------
#define ATT_THREADS 896
#define NCC 8
__global__ void __launch_bounds__(ATT_THREADS, 1)
k_att(const float* __restrict__ video, const float* __restrict__ Wv_b,
      const float* __restrict__ Wpv, const float* __restrict__ conv_w,
      const float* __restrict__ conv_b){
    __shared__ __align__(16) float Vs[2][NCC * NSPP];
    __shared__ __align__(16) float Ws[2][NCC * M_];
    __shared__ float sc[NSP];
    __shared__ float attb[NSP];
    __shared__ float cw[4 * C_];
    __shared__ float wS[28][8];

    int t = blockIdx.x;
    int bs = t / P_;
    const float* V = video + (size_t)t * (C_ * NSP);
    int tid = threadIdx.x;
    int tj = tid & 15, ti = tid >> 4;     // ti 0..55
    int m0 = tj * 8, n0 = ti * 4;

    for (int i = tid; i < 4 * C_; i += ATT_THREADS) cw[i] = conv_w[i];

    int wst[2];
    #pragma unroll
    for (int r = 0; r < 2; r++){
        int idx = tid + r * ATT_THREADS;
        if (idx < NCC * M_){
            int cc = idx >> 7, m = idx & 127;
            int p = m >> 1;
            int q = ((p & 3) << 4) | (p >> 2);
            wst[r] = cc * M_ + q * 2 + (m & 1);
        } else wst[r] = -1;
    }

    #pragma unroll
    for (int r = 0; r < 2; r++){
        int idx = tid + r * ATT_THREADS;
        int cc = idx / NSPP, col = idx - cc * NSPP;
        Vs[0][idx] = (col < NSP) ? V[cc * NSP + col] : 0.0f;
    }
    #pragma unroll
    for (int r = 0; r < 2; r++)
        if (wst[r] >= 0) Ws[0][wst[r]] = g_Wt[tid + r * ATT_THREADS];
    __syncthreads();

    unsigned long long acc[4][4];
    #pragma unroll
    for (int i = 0; i < 4; i++)
        #pragma unroll
        for (int j = 0; j < 4; j++) acc[i][j] = 0ULL;

    const int NSTAGE = C_ / NCC; // 66
    for (int st = 0; st < NSTAGE; st++){
        int cur = st & 1;
        float vtmp[2], wtmp[2];
        bool has = (st + 1 < NSTAGE);
        if (has){
            const float* Vn = V + (st + 1) * (NCC * NSP);
            const float* Wn = g_Wt + (st + 1) * (NCC * M_);
            #pragma unroll
            for (int r = 0; r < 2; r++){
                int idx = tid + r * ATT_THREADS;
                int cc = idx / NSPP, col = idx - cc * NSPP;
                vtmp[r] = (col < NSP) ? Vn[cc * NSP + col] : 0.0f;
            }
            #pragma unroll
            for (int r = 0; r < 2; r++)
                wtmp[r] = (wst[r] >= 0) ? Wn[tid + r * ATT_THREADS] : 0.0f;
        }
        const float* vsc = Vs[cur];
        const unsigned long long* wsc = reinterpret_cast<const unsigned long long*>(Ws[cur]);
        #pragma unroll
        for (int cc = 0; cc < NCC; cc++){
            unsigned long long bv[4];
            #pragma unroll
            for (int j = 0; j < 4; j++) bv[j] = wsc[cc * 64 + j * 16 + tj];
            float4 a4 = *reinterpret_cast<const float4*>(vsc + cc * NSPP + n0);
            unsigned long long av0 = pack2(a4.x, a4.x);
            unsigned long long av1 = pack2(a4.y, a4.y);
            unsigned long long av2 = pack2(a4.z, a4.z);
            unsigned long long av3 = pack2(a4.w, a4.w);
            #pragma unroll
            for (int j = 0; j < 4; j++){
                fma2(acc[0][j], av0, bv[j]);
                fma2(acc[1][j], av1, bv[j]);
                fma2(acc[2][j], av2, bv[j]);
                fma2(acc[3][j], av3, bv[j]);
            }
        }
        if (has){
            float* vd = Vs[cur ^ 1];
            float* wd = Ws[cur ^ 1];
            #pragma unroll
            for (int r = 0; r < 2; r++){
                int idx = tid + r * ATT_THREADS;
                vd[idx] = vtmp[r];
            }
            #pragma unroll
            for (int r = 0; r < 2; r++)
                if (wst[r] >= 0) wd[wst[r]] = wtmp[r];
        }
        __syncthreads();
    }

    const float* pa = g_patt + (size_t)bs * M_;
    float sp[4] = {0,0,0,0};
    #pragma unroll
    for (int j = 0; j < 4; j++){
        int m = m0 + 2 * j;
        float2 pv = *reinterpret_cast<const float2*>(pa + m);
        float2 bb = *reinterpret_cast<const float2*>(Wv_b + m);
        float2 ww = *reinterpret_cast<const float2*>(Wpv + m);
        #pragma unroll
        for (int i = 0; i < 4; i++){
            float x, y; unpack2(acc[i][j], x, y);
            x = tanh_fast(x + pv.x + bb.x);
            y = tanh_fast(y + pv.y + bb.y);
            sp[i] += x * ww.x + y * ww.y;
        }
    }
    #pragma unroll
    for (int o = 8; o >= 1; o >>= 1)
        #pragma unroll
        for (int i = 0; i < 4; i++)
            sp[i] += __shfl_xor_sync(0xffffffffu, sp[i], o);
    if (tj == 0 && n0 < NSP){
        #pragma unroll
        for (int i = 0; i < 4; i++) sc[n0 + i] = sp[i];
    }
    __syncthreads();

    if (tid < 32){
        float mx = -3.4e38f;
        for (int n = tid; n < NSP; n += 32) mx = fmaxf(mx, sc[n]);
        #pragma unroll
        for (int o = 16; o; o >>= 1) mx = fmaxf(mx, __shfl_xor_sync(0xffffffffu, mx, o));
        float sm = 0.0f;
        for (int n = tid; n < NSP; n += 32){ float e = expf(sc[n] - mx); attb[n] = e; sm += e; }
        #pragma unroll
        for (int o = 16; o; o >>= 1) sm += __shfl_xor_sync(0xffffffffu, sm, o);
        float inv = 1.0f / sm;
        for (int n = tid; n < NSP; n += 32) attb[n] *= inv;
    }
    __syncthreads();

    float d0 = 0.f, d1 = 0.f, d2 = 0.f, d3 = 0.f;
    int n = tid >> 1, half = tid & 1;
    if (tid < 392){
        const float4* fp = reinterpret_cast<const float4*>(V + (size_t)n * C_ + half * 264);
        #pragma unroll 4
        for (int q = 0; q < 66; q++){
            float4 v4 = fp[q];
            int c = half * 264 + q * 4;
            d0 += v4.x*cw[c]       + v4.y*cw[c+1]       + v4.z*cw[c+2]       + v4.w*cw[c+3];
            d1 += v4.x*cw[528+c]   + v4.y*cw[528+c+1]   + v4.z*cw[528+c+2]   + v4.w*cw[528+c+3];
            d2 += v4.x*cw[1056+c]  + v4.y*cw[1056+c+1]  + v4.z*cw[1056+c+2]  + v4.w*cw[1056+c+3];
            d3 += v4.x*cw[1584+c]  + v4.y*cw[1584+c+1]  + v4.z*cw[1584+c+2]  + v4.w*cw[1584+c+3];
        }
    }
    d0 += __shfl_xor_sync(0xffffffffu, d0, 1);
    d1 += __shfl_xor_sync(0xffffffffu, d1, 1);
    d2 += __shfl_xor_sync(0xffffffffu, d2, 1);
    d3 += __shfl_xor_sync(0xffffffffu, d3, 1);

    float dsum[4] = {0,0,0,0}, dsq[4] = {0,0,0,0};
    if (tid < 392 && half == 0){
        float an = attb[n];
        float vv[4];
        vv[0] = an * d0 + conv_b[0];
        vv[1] = an * d1 + conv_b[1];
        vv[2] = an * d2 + conv_b[2];
        vv[3] = an * d3 + conv_b[3];
        #pragma unroll
        for (int o = 0; o < 4; o++){
            g_vidpre[(size_t)t * 784 + o * NSP + n] = vv[o];
            dsum[o] = vv[o];
            dsq[o] = vv[o] * vv[o];
        }
    }
    #pragma unroll
    for (int o = 0; o < 4; o++){
        #pragma unroll
        for (int sh = 16; sh; sh >>= 1){
            dsum[o] += __shfl_down_sync(0xffffffffu, dsum[o], sh);
            dsq[o]  += __shfl_down_sync(0xffffffffu, dsq[o], sh);
        }
    }
    int wid = tid >> 5, lane = tid & 31;
    if (lane == 0){
        #pragma unroll
        for (int o = 0; o < 4; o++){ wS[wid][o] = dsum[o]; wS[wid][4 + o] = dsq[o]; }
    }
    __syncthreads();
    if (tid < 8){
        float a = 0.f;
        #pragma unroll
        for (int w = 0; w < 28; w++) a += wS[w][tid];
        g_bnPart[t * 8 + tid] = a;
    }
}

// ---------- motion BN stats over 256 rows ----------
__global__ void k_mstats(){
    int m = threadIdx.x;
    float sum = 0.f, sq = 0.f;
    for (int r = 0; r < BSN; r++){
        float v = g_mot[r * M_ + m];
        sum += v; sq += v * v;
    }
    float mu = sum / (float)BSN;
    float var = sq / (float)BSN - mu * mu;
    g_mstats[m] = mu;
    g_mstats[M_ + m] = rsqrtf(var + 1e-5f);
}

// ---------- video BN stats reduce ----------
__global__ void k_vstats(){
    __shared__ float red[256];
    __shared__ float tot[8];
    int tid = threadIdx.x;
    float part[8] = {0,0,0,0,0,0,0,0};
    for (int t = tid; t < TOT; t += 256)
        #pragma unroll
        for (int k = 0; k < 8; k++) part[k] += g_bnPart[t * 8 + k];
    for (int k = 0; k < 8; k++){
        red[tid] = part[k];
        __syncthreads();
        for (int o = 128; o; o >>= 1){
            if (tid < o) red[tid] += red[tid + o];
            __syncthreads();
        }
        if (tid == 0) tot[k] = red[0];
        __syncthreads();
    }
    if (tid < 4){
        float cnt = (float)TOT * (float)NSP;
        float mu = tot[tid] / cnt;
        float var = tot[4 + tid] / cnt - mu * mu;
        g_vstats[tid] = mu;
        g_vstats[4 + tid] = rsqrtf(var + 1e-5f);
    }
}

// ---------- final assembly ----------
__global__ void k_final(const float* __restrict__ tw,
                        const float* __restrict__ vbn_g, const float* __restrict__ vbn_b,
                        const float* __restrict__ mbn_g, const float* __restrict__ mbn_b,
                        float* __restrict__ out){
    int t = blockIdx.x, bs = t / P_, p = t % P_;
    float* o = out + (size_t)t * OUTW;
    for (int c = threadIdx.x; c < OUTW; c += 256){
        float v;
        if (c == 0) v = tw[p];
        else if (c < 785) v = g_pref[(size_t)bs * H_ + (c - 1)];
        else if (c < 913){
            int m = c - 785;
            float x = g_mot[bs * M_ + m];
            v = fmaxf((x - g_mstats[m]) * g_mstats[M_ + m] * mbn_g[m] + mbn_b[m], 0.f);
        } else {
            int idx = c - 913, ch = idx / NSP;
            float x = g_vidpre[(size_t)t * 784 + idx];
            v = fmaxf((x - g_vstats[ch]) * g_vstats[4 + ch] * vbn_g[ch] + vbn_b[ch], 0.f);
        }
        o[c] = v;
    }
}

// ---------- launcher ----------
extern "C" void kernel_launch(void* const* d_in, const int* in_sizes, int n_in,
                              void* d_out, int out_size){
    const float* fov      = (const float*)d_in[0];
    const float* motion   = (const float*)d_in[1];
    const float* video    = (const float*)d_in[2];
    const float* timew    = (const float*)d_in[3];
    const float* gru_w_ih = (const float*)d_in[4];
    const float* gru_w_hh = (const float*)d_in[5];
    const float* gru_b_ih = (const float*)d_in[6];
    const float* gru_b_hh = (const float*)d_in[7];
    const float* Wp       = (const float*)d_in[8];
    const float* Wv_w     = (const float*)d_in[9];
    const float* Wv_b     = (const float*)d_in[10];
    const float* Wpv_w    = (const float*)d_in[11];
    const float* conv_w   = (const float*)d_in[13];
    const float* conv_b   = (const float*)d_in[14];
    const float* vbn_g    = (const float*)d_in[15];
    const float* vbn_b    = (const float*)d_in[16];
    const float* me_w     = (const float*)d_in[17];
    const float* me_b     = (const float*)d_in[18];
    const float* mbn_g    = (const float*)d_in[19];
    const float* mbn_b    = (const float*)d_in[20];
    float* out = (float*)d_out;

    k_prep<<<264, 256>>>(Wv_w);                                           // 1
    k_gemm_nt<<<dim3(37, 8), 256>>>(fov, gru_w_ih, gru_b_ih, 0,
                                    BSN, 3 * H_, C_);                     // 2
    k_gru_all<<<GRU_NCTA, GRU_THREADS>>>(gru_w_hh, gru_b_hh, Wp);         // 3 (incl. p_att)
    k_att<<<TOT, ATT_THREADS>>>(video, Wv_b, Wpv_w, conv_w, conv_b);      // 4 -> ncu capture
    k_gemm_nt<<<dim3(2, 8), 256>>>(motion, me_w, me_b, 2,
                                   BSN, M_, 90);                          // 5
    k_mstats<<<1, 128>>>();
    k_vstats<<<1, 256>>>();
    k_final<<<TOT, 256>>>(timew, vbn_g, vbn_b, mbn_g, mbn_b, out);
}

// round 13
// speedup vs baseline: 1.6854x; 1.5241x over previous
#include <cuda_runtime.h>
#include <cuda_bf16.h>
#include <math.h>
#include <stdint.h>

#define DINL __device__ __forceinline__

// ---------- packed fp32x2 helpers (sm_103a) ----------
DINL unsigned long long pack2(float x, float y){
    unsigned long long r;
    asm("mov.b64 %0, {%1,%2};" : "=l"(r) : "f"(x), "f"(y));
    return r;
}
DINL void unpack2(unsigned long long v, float& x, float& y){
    asm("mov.b64 {%0,%1}, %2;" : "=f"(x), "=f"(y) : "l"(v));
}
DINL void fma2(unsigned long long& d, unsigned long long a, unsigned long long b){
    asm("fma.rn.f32x2 %0, %1, %2, %0;" : "+l"(d) : "l"(a), "l"(b));
}
DINL float sigm(float x){ return 1.0f / (1.0f + expf(-x)); }
DINL float tanh_fast(float x){
    float y;
    asm("tanh.approx.f32 %0, %1;" : "=f"(y) : "f"(x));
    return y;
}
DINL uint32_t smem_u32(const void* p){
    uint32_t a;
    asm("{ .reg .u64 t; cvta.to.shared.u64 t, %1; cvt.u32.u64 %0, t; }" : "=r"(a) : "l"(p));
    return a;
}
DINL void ldsm4(uint32_t* r, uint32_t addr){
    asm volatile("ldmatrix.sync.aligned.m8n8.x4.shared.b16 {%0,%1,%2,%3},[%4];"
        : "=r"(r[0]), "=r"(r[1]), "=r"(r[2]), "=r"(r[3]) : "r"(addr));
}
DINL void ldsm4t(uint32_t* r, uint32_t addr){
    asm volatile("ldmatrix.sync.aligned.m8n8.x4.trans.shared.b16 {%0,%1,%2,%3},[%4];"
        : "=r"(r[0]), "=r"(r[1]), "=r"(r[2]), "=r"(r[3]) : "r"(addr));
}
DINL void mma_bf16(float* d, const uint32_t* a, const uint32_t* b){
    asm volatile("mma.sync.aligned.m16n8k16.row.col.f32.bf16.bf16.f32 "
        "{%0,%1,%2,%3},{%4,%5,%6,%7},{%8,%9},{%0,%1,%2,%3};"
        : "+f"(d[0]), "+f"(d[1]), "+f"(d[2]), "+f"(d[3])
        : "r"(a[0]), "r"(a[1]), "r"(a[2]), "r"(a[3]), "r"(b[0]), "r"(b[1]));
}
DINL uint32_t packbf(float x, float y){
    __nv_bfloat162 t = __floats2bfloat162_rn(x, y);
    return *reinterpret_cast<uint32_t*>(&t);
}

// ---------- sizes ----------
#define B_   8
#define S_   32
#define P_   5
#define C_   528
#define H_   784
#define M_   128
#define NSP  196
#define TOT  1280
#define BSN  256
#define OUTW 1697

// k_att MMA config
#define NPAD 232          // Vs row stride in bf16 (29*16B -> conflict-free LDSM)
#define WPAD 24           // Ws row stride in bf16 (3*16B -> conflict-free LDSM)
#define KC   16
#define NCHUNK 33         // 528/16
#define VH_OFF 0
#define VL_OFF 7424       // 16*232*2
#define WH_OFF 14848
#define WL_OFF 20992      // +128*24*2
#define BUFSZ  27136
#define ATT_DSMEM (2*BUFSZ)

// ---------- device scratch ----------
__device__ __align__(16) float g_GI[BSN * 3 * H_];
__device__ __align__(16) float g_h[2][B_ * H_];
__device__ __align__(16) float g_pref[BSN * H_];
__device__ __align__(16) float g_patt[BSN * M_];
__device__ __align__(16) float g_mot[BSN * M_];
__device__ __align__(16) __nv_bfloat16 g_Wh[M_ * C_];
__device__ __align__(16) __nv_bfloat16 g_Wl[M_ * C_];
__device__ __align__(16) float g_vidpre[(size_t)TOT * 784];
__device__ __align__(16) float g_bnPart[TOT * 8];
__device__ __align__(16) float g_mstats[2 * M_];
__device__ __align__(16) float g_vstats[8];
__device__ unsigned g_bar;

// ---------- prep: split Wv_w into bf16 hi/lo; reset barrier ----------
__global__ void k_prep(const float* __restrict__ Wv_w){
    int i = blockIdx.x * 256 + threadIdx.x;
    if (i < C_ * M_){
        float w = Wv_w[i];
        __nv_bfloat16 h = __float2bfloat16(w);
        g_Wh[i] = h;
        g_Wl[i] = __float2bfloat16(w - __bfloat162float(h));
    }
    if (i == 0) g_bar = 0u;
}

// ---------- generic NT GEMM, double-buffered (GI / mot) ----------
__global__ void k_gemm_nt(const float* __restrict__ Aext, const float* __restrict__ Bm,
                          const float* __restrict__ bias, int ctag,
                          int M, int N, int K){
    const float* A = Aext;
    float* C = (ctag == 0) ? g_GI : g_mot;
    __shared__ float As[32][33];
    __shared__ float Bs[64][33];
    int i0 = blockIdx.y * 32, j0 = blockIdx.x * 64;
    int tid = threadIdx.x;
    int ti = tid >> 4, tj = tid & 15;

    int ar[4], ac[4], br[8], bc[8];
    #pragma unroll
    for (int r = 0; r < 4; r++){ int idx = tid + r * 256; ar[r] = idx >> 5; ac[r] = idx & 31; }
    #pragma unroll
    for (int r = 0; r < 8; r++){ int idx = tid + r * 256; br[r] = idx >> 5; bc[r] = idx & 31; }

    float a_reg[4], b_reg[8];
    #pragma unroll
    for (int r = 0; r < 4; r++){
        float v = 0.0f;
        if (i0 + ar[r] < M && ac[r] < K) v = A[(size_t)(i0 + ar[r]) * K + ac[r]];
        a_reg[r] = v;
    }
    #pragma unroll
    for (int r = 0; r < 8; r++){
        float v = 0.0f;
        if (j0 + br[r] < N && bc[r] < K) v = Bm[(size_t)(j0 + br[r]) * K + bc[r]];
        b_reg[r] = v;
    }

    float acc[2][4] = {{0,0,0,0},{0,0,0,0}};
    for (int k0 = 0; k0 < K; k0 += 32){
        #pragma unroll
        for (int r = 0; r < 4; r++) As[ar[r]][ac[r]] = a_reg[r];
        #pragma unroll
        for (int r = 0; r < 8; r++) Bs[br[r]][bc[r]] = b_reg[r];
        __syncthreads();

        int kn = k0 + 32;
        if (kn < K){
            #pragma unroll
            for (int r = 0; r < 4; r++){
                float v = 0.0f;
                if (i0 + ar[r] < M && kn + ac[r] < K) v = A[(size_t)(i0 + ar[r]) * K + kn + ac[r]];
                a_reg[r] = v;
            }
            #pragma unroll
            for (int r = 0; r < 8; r++){
                float v = 0.0f;
                if (j0 + br[r] < N && kn + bc[r] < K) v = Bm[(size_t)(j0 + br[r]) * K + kn + bc[r]];
                b_reg[r] = v;
            }
        }

        #pragma unroll
        for (int kk = 0; kk < 32; kk++){
            float a0 = As[ti*2][kk], a1 = As[ti*2+1][kk];
            float b0 = Bs[tj*4][kk], b1 = Bs[tj*4+1][kk];
            float b2 = Bs[tj*4+2][kk], b3 = Bs[tj*4+3][kk];
            acc[0][0] += a0*b0; acc[0][1] += a0*b1; acc[0][2] += a0*b2; acc[0][3] += a0*b3;
            acc[1][0] += a1*b0; acc[1][1] += a1*b1; acc[1][2] += a1*b2; acc[1][3] += a1*b3;
        }
        __syncthreads();
    }
    #pragma unroll
    for (int r = 0; r < 2; r++)
        #pragma unroll
        for (int c = 0; c < 4; c++){
            int i = i0 + ti*2 + r, j = j0 + tj*4 + c;
            if (i < M && j < N){
                float v = acc[r][c];
                if (bias) v += bias[j];
                C[(size_t)i * N + j] = v;
            }
        }
}

// ---------- persistent GRU + fused p_att tail (unchanged from R12) ----------
#define GRU_NCTA 112
#define GRU_THREADS 672
#define GRU_JPC 7
__global__ void __launch_bounds__(GRU_THREADS)
k_gru_all(const float* __restrict__ Whh, const float* __restrict__ bhh,
          const float* __restrict__ Wp){
    __shared__ __align__(16) float4 hs4[B_ * (H_ / 4)];
    __shared__ float gsum[GRU_JPC][3][B_];
    int tid = threadIdx.x, wid = tid >> 5, lane = tid & 31;
    int jj = wid / 3, g = wid % 3;
    int j = blockIdx.x * GRU_JPC + jj;
    const float4* w = reinterpret_cast<const float4*>(Whh + (size_t)(g * H_ + j) * H_);
    float bj[3];
    if (tid < GRU_JPC * B_){
        int j2 = blockIdx.x * GRU_JPC + tid / B_;
        bj[0] = bhh[j2]; bj[1] = bhh[H_ + j2]; bj[2] = bhh[2 * H_ + j2];
    }

    for (int s = 0; s < S_; s++){
        const float* hin = g_h[s & 1];
        float* hout = g_h[(s + 1) & 1];

        if (s > 0){
            const float4* src = reinterpret_cast<const float4*>(hin);
            for (int i = tid; i < B_ * (H_ / 4); i += GRU_THREADS) hs4[i] = src[i];
        }
        __syncthreads();

        float red[B_];
        #pragma unroll
        for (int b = 0; b < B_; b++) red[b] = 0.0f;

        if (s > 0){
            float4 wv[7];
            #pragma unroll
            for (int it = 0; it < 7; it++){
                int k4 = lane + it * 32;
                if (it < 6 || lane < 4) wv[it] = w[k4];
                else                    wv[it] = make_float4(0.f, 0.f, 0.f, 0.f);
            }
            unsigned long long acc[B_];
            #pragma unroll
            for (int b = 0; b < B_; b++) acc[b] = 0ULL;
            #pragma unroll
            for (int it = 0; it < 7; it++){
                int k4 = lane + it * 32;
                bool ok = (it < 6 || lane < 4);
                unsigned long long wl = pack2(wv[it].x, wv[it].y);
                unsigned long long wh = pack2(wv[it].z, wv[it].w);
                if (ok){
                    #pragma unroll
                    for (int b = 0; b < B_; b++){
                        float4 h4 = hs4[b * (H_ / 4) + k4];
                        fma2(acc[b], wl, pack2(h4.x, h4.y));
                        fma2(acc[b], wh, pack2(h4.z, h4.w));
                    }
                }
            }
            #pragma unroll
            for (int b = 0; b < B_; b++){
                float x, y; unpack2(acc[b], x, y);
                red[b] = x + y;
            }
            #pragma unroll
            for (int o = 16; o; o >>= 1)
                #pragma unroll
                for (int b = 0; b < B_; b++)
                    red[b] += __shfl_down_sync(0xffffffffu, red[b], o);
        }
        if (lane == 0){
            #pragma unroll
            for (int b = 0; b < B_; b++) gsum[jj][g][b] = red[b];
        }
        __syncthreads();

        if (tid < GRU_JPC * B_){
            int jj2 = tid / B_, b = tid % B_;
            int j2 = blockIdx.x * GRU_JPC + jj2;
            int bs = b * S_ + s;
            const float* gi = g_GI + (size_t)bs * (3 * H_);
            const float* hsf = reinterpret_cast<const float*>(hs4);
            float r = sigm(gi[j2] + gsum[jj2][0][b] + bj[0]);
            float z = sigm(gi[H_ + j2] + gsum[jj2][1][b] + bj[1]);
            float n = tanhf(gi[2 * H_ + j2] + r * (gsum[jj2][2][b] + bj[2]));
            float hold = (s > 0) ? hsf[b * H_ + j2] : 0.0f;
            float hn = (1.0f - z) * n + z * hold;
            hout[b * H_ + j2] = hn;
            g_pref[(size_t)bs * H_ + j2] = hn;
        }

        __threadfence();
        __syncthreads();
        if (tid == 0){
            atomicAdd(&g_bar, 1u);
            unsigned target = (unsigned)GRU_NCTA * (unsigned)(s + 1);
            while (*((volatile unsigned*)&g_bar) < target) { }
        }
        __syncthreads();
        __threadfence();
    }

    // fused p_att tail
    float* prow = reinterpret_cast<float*>(hs4);
    int bsl[3]; int nbs = 0;
    for (int r = blockIdx.x; r < BSN; r += GRU_NCTA) bsl[nbs++] = r;
    __syncthreads();
    for (int i = tid; i < nbs * H_; i += GRU_THREADS){
        int r = i / H_, k = i - r * H_;
        prow[r * H_ + k] = g_pref[(size_t)bsl[r] * H_ + k];
    }
    __syncthreads();

    for (int m = wid; m < M_; m += (GRU_THREADS / 32)){
        const float4* wr = reinterpret_cast<const float4*>(Wp + (size_t)m * H_);
        float a[3] = {0.f, 0.f, 0.f};
        for (int k4 = lane; k4 < H_ / 4; k4 += 32){
            float4 w4 = wr[k4];
            for (int r = 0; r < nbs; r++){
                float4 p4 = reinterpret_cast<const float4*>(prow + r * H_)[k4];
                a[r] += p4.x * w4.x + p4.y * w4.y + p4.z * w4.z + p4.w * w4.w;
            }
        }
        #pragma unroll
        for (int o = 16; o; o >>= 1)
            for (int r = 0; r < 3; r++)
                a[r] += __shfl_down_sync(0xffffffffu, a[r], o);
        if (lane == 0)
            for (int r = 0; r < nbs; r++)
                g_patt[(size_t)bsl[r] * M_ + m] = a[r];
    }
}

// ---------- k_att: tensor-core (mma.sync bf16 split) + softmax + conv ----------
// One CTA per t, 896 threads = 28 warps. Warp w -> tile (nt = w%7, mt = w/7):
// n32 x m32 of raw[n,m] = sum_c V[c][n] * W[m][c].
// A = V^T via ldmatrix.trans from Vs[c][n]; B = W via plain ldmatrix from Ws[m][k].
// 3-term bf16 split: hh + hl + lh accumulated in fp32.
#define ATT_THREADS 896
__global__ void __launch_bounds__(ATT_THREADS, 1)
k_att(const float* __restrict__ video, const float* __restrict__ Wv_b,
      const float* __restrict__ Wpv, const float* __restrict__ conv_w,
      const float* __restrict__ conv_b){
    extern __shared__ char dsm[];
    __shared__ float cw[4 * C_];
    __shared__ float sc2[4 * 224];
    __shared__ float sc[NSP];
    __shared__ float attb[NSP];
    __shared__ float wS[28][8];

    int t = blockIdx.x;
    int bs = t / P_;
    const float* V = video + (size_t)t * (C_ * NSP);
    int tid = threadIdx.x;
    int w = tid >> 5, lane = tid & 31;
    int nt = w % 7, mt = w / 7;
    int n0w = nt * 32, m0w = mt * 32;
    uint32_t sbase = smem_u32(dsm);

    for (int i = tid; i < 4 * C_; i += ATT_THREADS) cw[i] = conv_w[i];

    // zero the n-pad region (196..231) of both V buffers, both splits (persists)
    for (int i = tid; i < 2 * 2 * 16 * 36; i += ATT_THREADS){
        int b = i / 1152, rem = i % 1152;
        int sp = rem / 576, rem2 = rem % 576;
        int c = rem2 / 36, nn = 196 + rem2 % 36;
        *reinterpret_cast<__nv_bfloat16*>(dsm + b * BUFSZ + sp * VL_OFF + (c * NPAD + nn) * 2)
            = __float2bfloat16(0.0f);
    }

    // per-thread staging constants
    bool vvalid = (tid < 784);
    int vc = tid / 49, vnb = tid % 49;                 // V: c-row, n-block(4)
    int widx0 = tid, widx1 = tid + 896, widx2 = tid + 1792;   // W uints (2048 total)
    const uint32_t* WHg = reinterpret_cast<const uint32_t*>(g_Wh);
    const uint32_t* WLg = reinterpret_cast<const uint32_t*>(g_Wl);

    // ldmatrix lane-local offsets
    int matA = lane >> 3;
    uint32_t a_local = (uint32_t)(((lane & 7) + (matA >> 1) * 8) * NPAD + n0w + (matA & 1) * 8) * 2;
    int matB = lane >> 3;
    uint32_t b_local = (uint32_t)((m0w + (matB >> 1) * 8 + (lane & 7)) * WPAD) * 2 + (matB & 1) * 16;

    // prefetch chunk 0
    float4 vreg = make_float4(0.f, 0.f, 0.f, 0.f);
    uint32_t wreg0 = 0, wreg1 = 0, wreg2 = 0;
    {
        if (vvalid) vreg = *reinterpret_cast<const float4*>(V + vc * NSP + vnb * 4);
        {
            int half = widx0 >> 10, wi = widx0 & 1023, m = wi >> 3, k2 = wi & 7;
            wreg0 = (half ? WLg : WHg)[m * 264 + 0 * 8 + k2];
        }
        {
            int half = widx1 >> 10, wi = widx1 & 1023, m = wi >> 3, k2 = wi & 7;
            wreg1 = (half ? WLg : WHg)[m * 264 + 0 * 8 + k2];
        }
        if (widx2 < 2048){
            int half = widx2 >> 10, wi = widx2 & 1023, m = wi >> 3, k2 = wi & 7;
            wreg2 = (half ? WLg : WHg)[m * 264 + 0 * 8 + k2];
        }
    }

    float dacc[2][4][4];
    #pragma unroll
    for (int i = 0; i < 2; i++)
        #pragma unroll
        for (int j = 0; j < 4; j++)
            #pragma unroll
            for (int k = 0; k < 4; k++) dacc[i][j][k] = 0.0f;

    for (int kc = 0; kc < NCHUNK; kc++){
        int buf = kc & 1;
        char* sb = dsm + buf * BUFSZ;
        // store staged chunk
        if (vvalid){
            __nv_bfloat16 h0 = __float2bfloat16(vreg.x);
            __nv_bfloat16 h1 = __float2bfloat16(vreg.y);
            __nv_bfloat16 h2 = __float2bfloat16(vreg.z);
            __nv_bfloat16 h3 = __float2bfloat16(vreg.w);
            float l0 = vreg.x - __bfloat162float(h0);
            float l1 = vreg.y - __bfloat162float(h1);
            float l2 = vreg.z - __bfloat162float(h2);
            float l3 = vreg.w - __bfloat162float(h3);
            uint32_t hu0, hu1;
            { __nv_bfloat162 p = __halves2bfloat162(h0, h1); hu0 = *reinterpret_cast<uint32_t*>(&p); }
            { __nv_bfloat162 p = __halves2bfloat162(h2, h3); hu1 = *reinterpret_cast<uint32_t*>(&p); }
            uint2 hp = make_uint2(hu0, hu1);
            uint2 lp = make_uint2(packbf(l0, l1), packbf(l2, l3));
            *reinterpret_cast<uint2*>(sb + VH_OFF + (vc * NPAD + vnb * 4) * 2) = hp;
            *reinterpret_cast<uint2*>(sb + VL_OFF + (vc * NPAD + vnb * 4) * 2) = lp;
        }
        {
            int half = widx0 >> 10, wi = widx0 & 1023, m = wi >> 3, k2 = wi & 7;
            reinterpret_cast<uint32_t*>(sb + (half ? WL_OFF : WH_OFF))[m * 12 + k2] = wreg0;
        }
        {
            int half = widx1 >> 10, wi = widx1 & 1023, m = wi >> 3, k2 = wi & 7;
            reinterpret_cast<uint32_t*>(sb + (half ? WL_OFF : WH_OFF))[m * 12 + k2] = wreg1;
        }
        if (widx2 < 2048){
            int half = widx2 >> 10, wi = widx2 & 1023, m = wi >> 3, k2 = wi & 7;
            reinterpret_cast<uint32_t*>(sb + (half ? WL_OFF : WH_OFF))[m * 12 + k2] = wreg2;
        }
        __syncthreads();

        // prefetch next chunk
        if (kc + 1 < NCHUNK){
            int kn = kc + 1;
            if (vvalid) vreg = *reinterpret_cast<const float4*>(V + (kn * KC + vc) * NSP + vnb * 4);
            {
                int half = widx0 >> 10, wi = widx0 & 1023, m = wi >> 3, k2 = wi & 7;
                wreg0 = (half ? WLg : WHg)[m * 264 + kn * 8 + k2];
            }
            {
                int half = widx1 >> 10, wi = widx1 & 1023, m = wi >> 3, k2 = wi & 7;
                wreg1 = (half ? WLg : WHg)[m * 264 + kn * 8 + k2];
            }
            if (widx2 < 2048){
                int half = widx2 >> 10, wi = widx2 & 1023, m = wi >> 3, k2 = wi & 7;
                wreg2 = (half ? WLg : WHg)[m * 264 + kn * 8 + k2];
            }
        }

        // MMA on current chunk
        uint32_t sbb = sbase + buf * BUFSZ;
        uint32_t bh[8], bl[8];
        ldsm4(bh,     sbb + WH_OFF + b_local);
        ldsm4(bh + 4, sbb + WH_OFF + b_local + 16 * WPAD * 2);
        ldsm4(bl,     sbb + WL_OFF + b_local);
        ldsm4(bl + 4, sbb + WL_OFF + b_local + 16 * WPAD * 2);
        #pragma unroll
        for (int nsub = 0; nsub < 2; nsub++){
            uint32_t af[4];
            ldsm4t(af, sbb + VH_OFF + a_local + nsub * 32);
            #pragma unroll
            for (int ms = 0; ms < 4; ms++) mma_bf16(dacc[nsub][ms], af, bh + ms * 2);
            #pragma unroll
            for (int ms = 0; ms < 4; ms++) mma_bf16(dacc[nsub][ms], af, bl + ms * 2);
            ldsm4t(af, sbb + VL_OFF + a_local + nsub * 32);
            #pragma unroll
            for (int ms = 0; ms < 4; ms++) mma_bf16(dacc[nsub][ms], af, bh + ms * 2);
        }
        __syncthreads();
    }

    // ---- epilogue: scores ----
    const float* pa = g_patt + (size_t)bs * M_;
    float rs[2][2] = {{0.f, 0.f}, {0.f, 0.f}};
    #pragma unroll
    for (int nsub = 0; nsub < 2; nsub++)
        #pragma unroll
        for (int ms = 0; ms < 4; ms++){
            int m0 = m0w + ms * 8 + 2 * (lane & 3);
            float pv0 = pa[m0] + Wv_b[m0], pv1 = pa[m0 + 1] + Wv_b[m0 + 1];
            float w0 = Wpv[m0], w1 = Wpv[m0 + 1];
            const float* d = dacc[nsub][ms];
            rs[nsub][0] += tanh_fast(d[0] + pv0) * w0 + tanh_fast(d[1] + pv1) * w1;
            rs[nsub][1] += tanh_fast(d[2] + pv0) * w0 + tanh_fast(d[3] + pv1) * w1;
        }
    #pragma unroll
    for (int o = 1; o <= 2; o <<= 1)
        #pragma unroll
        for (int nsub = 0; nsub < 2; nsub++)
            #pragma unroll
            for (int h = 0; h < 2; h++)
                rs[nsub][h] += __shfl_xor_sync(0xffffffffu, rs[nsub][h], o);
    if ((lane & 3) == 0){
        int la = lane >> 2;
        #pragma unroll
        for (int nsub = 0; nsub < 2; nsub++)
            #pragma unroll
            for (int h = 0; h < 2; h++)
                sc2[mt * 224 + n0w + nsub * 16 + h * 8 + la] = rs[nsub][h];
    }
    __syncthreads();
    if (tid < NSP)
        sc[tid] = sc2[tid] + sc2[224 + tid] + sc2[448 + tid] + sc2[672 + tid];
    __syncthreads();

    // softmax over 196 (warp 0)
    if (tid < 32){
        float mx = -3.4e38f;
        for (int n = tid; n < NSP; n += 32) mx = fmaxf(mx, sc[n]);
        #pragma unroll
        for (int o = 16; o; o >>= 1) mx = fmaxf(mx, __shfl_xor_sync(0xffffffffu, mx, o));
        float sm = 0.0f;
        for (int n = tid; n < NSP; n += 32){ float e = expf(sc[n] - mx); attb[n] = e; sm += e; }
        #pragma unroll
        for (int o = 16; o; o >>= 1) sm += __shfl_xor_sync(0xffffffffu, sm, o);
        float inv = 1.0f / sm;
        for (int n = tid; n < NSP; n += 32) attb[n] *= inv;
    }
    __syncthreads();

    // ---- 1x1 conv on the OTHER reinterpretation: flat[n*528+c], weighted ----
    float d0 = 0.f, d1 = 0.f, d2 = 0.f, d3 = 0.f;
    int n = tid >> 1, half = tid & 1;
    if (tid < 392){
        const float4* fp = reinterpret_cast<const float4*>(V + (size_t)n * C_ + half * 264);
        #pragma unroll 4
        for (int q = 0; q < 66; q++){
            float4 v4 = fp[q];
            int c = half * 264 + q * 4;
            d0 += v4.x*cw[c]       + v4.y*cw[c+1]       + v4.z*cw[c+2]       + v4.w*cw[c+3];
            d1 += v4.x*cw[528+c]   + v4.y*cw[528+c+1]   + v4.z*cw[528+c+2]   + v4.w*cw[528+c+3];
            d2 += v4.x*cw[1056+c]  + v4.y*cw[1056+c+1]  + v4.z*cw[1056+c+2]  + v4.w*cw[1056+c+3];
            d3 += v4.x*cw[1584+c]  + v4.y*cw[1584+c+1]  + v4.z*cw[1584+c+2]  + v4.w*cw[1584+c+3];
        }
    }
    d0 += __shfl_xor_sync(0xffffffffu, d0, 1);
    d1 += __shfl_xor_sync(0xffffffffu, d1, 1);
    d2 += __shfl_xor_sync(0xffffffffu, d2, 1);
    d3 += __shfl_xor_sync(0xffffffffu, d3, 1);

    float dsum[4] = {0,0,0,0}, dsq[4] = {0,0,0,0};
    if (tid < 392 && half == 0){
        float an = attb[n];
        float vv[4];
        vv[0] = an * d0 + conv_b[0];
        vv[1] = an * d1 + conv_b[1];
        vv[2] = an * d2 + conv_b[2];
        vv[3] = an * d3 + conv_b[3];
        #pragma unroll
        for (int o = 0; o < 4; o++){
            g_vidpre[(size_t)t * 784 + o * NSP + n] = vv[o];
            dsum[o] = vv[o];
            dsq[o] = vv[o] * vv[o];
        }
    }
    #pragma unroll
    for (int o = 0; o < 4; o++){
        #pragma unroll
        for (int sh = 16; sh; sh >>= 1){
            dsum[o] += __shfl_down_sync(0xffffffffu, dsum[o], sh);
            dsq[o]  += __shfl_down_sync(0xffffffffu, dsq[o], sh);
        }
    }
    if (lane == 0){
        #pragma unroll
        for (int o = 0; o < 4; o++){ wS[w][o] = dsum[o]; wS[w][4 + o] = dsq[o]; }
    }
    __syncthreads();
    if (tid < 8){
        float a = 0.f;
        #pragma unroll
        for (int ww = 0; ww < 28; ww++) a += wS[ww][tid];
        g_bnPart[t * 8 + tid] = a;
    }
}

// ---------- motion BN stats ----------
__global__ void k_mstats(){
    int m = threadIdx.x;
    float sum = 0.f, sq = 0.f;
    for (int r = 0; r < BSN; r++){
        float v = g_mot[r * M_ + m];
        sum += v; sq += v * v;
    }
    float mu = sum / (float)BSN;
    float var = sq / (float)BSN - mu * mu;
    g_mstats[m] = mu;
    g_mstats[M_ + m] = rsqrtf(var + 1e-5f);
}

// ---------- video BN stats reduce ----------
__global__ void k_vstats(){
    __shared__ float red[256];
    __shared__ float tot[8];
    int tid = threadIdx.x;
    float part[8] = {0,0,0,0,0,0,0,0};
    for (int t = tid; t < TOT; t += 256)
        #pragma unroll
        for (int k = 0; k < 8; k++) part[k] += g_bnPart[t * 8 + k];
    for (int k = 0; k < 8; k++){
        red[tid] = part[k];
        __syncthreads();
        for (int o = 128; o; o >>= 1){
            if (tid < o) red[tid] += red[tid + o];
            __syncthreads();
        }
        if (tid == 0) tot[k] = red[0];
        __syncthreads();
    }
    if (tid < 4){
        float cnt = (float)TOT * (float)NSP;
        float mu = tot[tid] / cnt;
        float var = tot[4 + tid] / cnt - mu * mu;
        g_vstats[tid] = mu;
        g_vstats[4 + tid] = rsqrtf(var + 1e-5f);
    }
}

// ---------- final assembly ----------
__global__ void k_final(const float* __restrict__ tw,
                        const float* __restrict__ vbn_g, const float* __restrict__ vbn_b,
                        const float* __restrict__ mbn_g, const float* __restrict__ mbn_b,
                        float* __restrict__ out){
    int t = blockIdx.x, bs = t / P_, p = t % P_;
    float* o = out + (size_t)t * OUTW;
    for (int c = threadIdx.x; c < OUTW; c += 256){
        float v;
        if (c == 0) v = tw[p];
        else if (c < 785) v = g_pref[(size_t)bs * H_ + (c - 1)];
        else if (c < 913){
            int m = c - 785;
            float x = g_mot[bs * M_ + m];
            v = fmaxf((x - g_mstats[m]) * g_mstats[M_ + m] * mbn_g[m] + mbn_b[m], 0.f);
        } else {
            int idx = c - 913, ch = idx / NSP;
            float x = g_vidpre[(size_t)t * 784 + idx];
            v = fmaxf((x - g_vstats[ch]) * g_vstats[4 + ch] * vbn_g[ch] + vbn_b[ch], 0.f);
        }
        o[c] = v;
    }
}

// ---------- launcher ----------
extern "C" void kernel_launch(void* const* d_in, const int* in_sizes, int n_in,
                              void* d_out, int out_size){
    const float* fov      = (const float*)d_in[0];
    const float* motion   = (const float*)d_in[1];
    const float* video    = (const float*)d_in[2];
    const float* timew    = (const float*)d_in[3];
    const float* gru_w_ih = (const float*)d_in[4];
    const float* gru_w_hh = (const float*)d_in[5];
    const float* gru_b_ih = (const float*)d_in[6];
    const float* gru_b_hh = (const float*)d_in[7];
    const float* Wp       = (const float*)d_in[8];
    const float* Wv_w     = (const float*)d_in[9];
    const float* Wv_b     = (const float*)d_in[10];
    const float* Wpv_w    = (const float*)d_in[11];
    const float* conv_w   = (const float*)d_in[13];
    const float* conv_b   = (const float*)d_in[14];
    const float* vbn_g    = (const float*)d_in[15];
    const float* vbn_b    = (const float*)d_in[16];
    const float* me_w     = (const float*)d_in[17];
    const float* me_b     = (const float*)d_in[18];
    const float* mbn_g    = (const float*)d_in[19];
    const float* mbn_b    = (const float*)d_in[20];
    float* out = (float*)d_out;

    static bool attr_done = false;
    if (!attr_done){
        cudaFuncSetAttribute(k_att, cudaFuncAttributeMaxDynamicSharedMemorySize, ATT_DSMEM);
        attr_done = true;
    }

    k_prep<<<264, 256>>>(Wv_w);                                              // 1
    k_gemm_nt<<<dim3(37, 8), 256>>>(fov, gru_w_ih, gru_b_ih, 0,
                                    BSN, 3 * H_, C_);                        // 2
    k_gru_all<<<GRU_NCTA, GRU_THREADS>>>(gru_w_hh, gru_b_hh, Wp);            // 3
    k_att<<<TOT, ATT_THREADS, ATT_DSMEM>>>(video, Wv_b, Wpv_w,
                                           conv_w, conv_b);                  // 4 -> ncu
    k_gemm_nt<<<dim3(2, 8), 256>>>(motion, me_w, me_b, 2, BSN, M_, 90);      // 5
    k_mstats<<<1, 128>>>();
    k_vstats<<<1, 256>>>();
    k_final<<<TOT, 256>>>(timew, vbn_g, vbn_b, mbn_g, mbn_b, out);
}

// round 14
// speedup vs baseline: 2.2011x; 1.3059x over previous
#include <cuda_runtime.h>
#include <cuda_bf16.h>
#include <math.h>
#include <stdint.h>

#define DINL __device__ __forceinline__

// ---------- packed fp32x2 helpers (sm_103a) ----------
DINL unsigned long long pack2(float x, float y){
    unsigned long long r;
    asm("mov.b64 %0, {%1,%2};" : "=l"(r) : "f"(x), "f"(y));
    return r;
}
DINL void unpack2(unsigned long long v, float& x, float& y){
    asm("mov.b64 {%0,%1}, %2;" : "=f"(x), "=f"(y) : "l"(v));
}
DINL void fma2(unsigned long long& d, unsigned long long a, unsigned long long b){
    asm("fma.rn.f32x2 %0, %1, %2, %0;" : "+l"(d) : "l"(a), "l"(b));
}
DINL float sigm(float x){ return 1.0f / (1.0f + expf(-x)); }
DINL float tanh_fast(float x){
    float y;
    asm("tanh.approx.f32 %0, %1;" : "=f"(y) : "f"(x));
    return y;
}
DINL uint32_t smem_u32(const void* p){
    uint32_t a;
    asm("{ .reg .u64 t; cvta.to.shared.u64 t, %1; cvt.u32.u64 %0, t; }" : "=r"(a) : "l"(p));
    return a;
}
DINL void ldsm4(uint32_t* r, uint32_t addr){
    asm volatile("ldmatrix.sync.aligned.m8n8.x4.shared.b16 {%0,%1,%2,%3},[%4];"
        : "=r"(r[0]), "=r"(r[1]), "=r"(r[2]), "=r"(r[3]) : "r"(addr));
}
DINL void ldsm4t(uint32_t* r, uint32_t addr){
    asm volatile("ldmatrix.sync.aligned.m8n8.x4.trans.shared.b16 {%0,%1,%2,%3},[%4];"
        : "=r"(r[0]), "=r"(r[1]), "=r"(r[2]), "=r"(r[3]) : "r"(addr));
}
DINL void mma_bf16(float* d, const uint32_t* a, const uint32_t* b){
    asm volatile("mma.sync.aligned.m16n8k16.row.col.f32.bf16.bf16.f32 "
        "{%0,%1,%2,%3},{%4,%5,%6,%7},{%8,%9},{%0,%1,%2,%3};"
        : "+f"(d[0]), "+f"(d[1]), "+f"(d[2]), "+f"(d[3])
        : "r"(a[0]), "r"(a[1]), "r"(a[2]), "r"(a[3]), "r"(b[0]), "r"(b[1]));
}
DINL uint32_t packbf(float x, float y){
    __nv_bfloat162 t = __floats2bfloat162_rn(x, y);
    return *reinterpret_cast<uint32_t*>(&t);
}

// ---------- sizes ----------
#define B_   8
#define S_   32
#define P_   5
#define C_   528
#define H_   784
#define M_   128
#define NSP  196
#define TOT  1280
#define BSN  256
#define OUTW 1697

// k_att MMA config
#define NPAD 232
#define WPAD 24
#define KC   16
#define NCHUNK 33
#define VH_OFF 0
#define VL_OFF 7424
#define WH_OFF 14848
#define WL_OFF 20992
#define BUFSZ  27136
#define ATT_DSMEM (2*BUFSZ)

// ---------- device scratch ----------
__device__ __align__(16) float g_GI[BSN * 3 * H_];
__device__ __align__(16) float g_h[2][B_ * H_];
__device__ __align__(16) float g_pref[BSN * H_];
__device__ __align__(16) float g_patt[BSN * M_];
__device__ __align__(16) float g_mot[BSN * M_];
__device__ __align__(16) __nv_bfloat16 g_Wh[M_ * C_];
__device__ __align__(16) __nv_bfloat16 g_Wl[M_ * C_];
__device__ __align__(16) float g_vidpre[(size_t)TOT * 784];
__device__ __align__(16) float g_bnPart[TOT * 8];
__device__ __align__(16) float g_mstats[2 * M_];
__device__ __align__(16) float g_vstats[8];
__device__ unsigned g_bar;

// ---------- prep: split Wv_w into bf16 hi/lo; reset barrier ----------
__global__ void k_prep(const float* __restrict__ Wv_w){
    int i = blockIdx.x * 256 + threadIdx.x;
    if (i < C_ * M_){
        float w = Wv_w[i];
        __nv_bfloat16 h = __float2bfloat16(w);
        g_Wh[i] = h;
        g_Wl[i] = __float2bfloat16(w - __bfloat162float(h));
    }
    if (i == 0) g_bar = 0u;
}

// ---------- generic NT GEMM, double-buffered (GI / mot) ----------
__global__ void k_gemm_nt(const float* __restrict__ Aext, const float* __restrict__ Bm,
                          const float* __restrict__ bias, int ctag,
                          int M, int N, int K){
    const float* A = Aext;
    float* C = (ctag == 0) ? g_GI : g_mot;
    __shared__ float As[32][33];
    __shared__ float Bs[64][33];
    int i0 = blockIdx.y * 32, j0 = blockIdx.x * 64;
    int tid = threadIdx.x;
    int ti = tid >> 4, tj = tid & 15;

    int ar[4], ac[4], br[8], bc[8];
    #pragma unroll
    for (int r = 0; r < 4; r++){ int idx = tid + r * 256; ar[r] = idx >> 5; ac[r] = idx & 31; }
    #pragma unroll
    for (int r = 0; r < 8; r++){ int idx = tid + r * 256; br[r] = idx >> 5; bc[r] = idx & 31; }

    float a_reg[4], b_reg[8];
    #pragma unroll
    for (int r = 0; r < 4; r++){
        float v = 0.0f;
        if (i0 + ar[r] < M && ac[r] < K) v = A[(size_t)(i0 + ar[r]) * K + ac[r]];
        a_reg[r] = v;
    }
    #pragma unroll
    for (int r = 0; r < 8; r++){
        float v = 0.0f;
        if (j0 + br[r] < N && bc[r] < K) v = Bm[(size_t)(j0 + br[r]) * K + bc[r]];
        b_reg[r] = v;
    }

    float acc[2][4] = {{0,0,0,0},{0,0,0,0}};
    for (int k0 = 0; k0 < K; k0 += 32){
        #pragma unroll
        for (int r = 0; r < 4; r++) As[ar[r]][ac[r]] = a_reg[r];
        #pragma unroll
        for (int r = 0; r < 8; r++) Bs[br[r]][bc[r]] = b_reg[r];
        __syncthreads();

        int kn = k0 + 32;
        if (kn < K){
            #pragma unroll
            for (int r = 0; r < 4; r++){
                float v = 0.0f;
                if (i0 + ar[r] < M && kn + ac[r] < K) v = A[(size_t)(i0 + ar[r]) * K + kn + ac[r]];
                a_reg[r] = v;
            }
            #pragma unroll
            for (int r = 0; r < 8; r++){
                float v = 0.0f;
                if (j0 + br[r] < N && kn + bc[r] < K) v = Bm[(size_t)(j0 + br[r]) * K + kn + bc[r]];
                b_reg[r] = v;
            }
        }

        #pragma unroll
        for (int kk = 0; kk < 32; kk++){
            float a0 = As[ti*2][kk], a1 = As[ti*2+1][kk];
            float b0 = Bs[tj*4][kk], b1 = Bs[tj*4+1][kk];
            float b2 = Bs[tj*4+2][kk], b3 = Bs[tj*4+3][kk];
            acc[0][0] += a0*b0; acc[0][1] += a0*b1; acc[0][2] += a0*b2; acc[0][3] += a0*b3;
            acc[1][0] += a1*b0; acc[1][1] += a1*b1; acc[1][2] += a1*b2; acc[1][3] += a1*b3;
        }
        __syncthreads();
    }
    #pragma unroll
    for (int r = 0; r < 2; r++)
        #pragma unroll
        for (int c = 0; c < 4; c++){
            int i = i0 + ti*2 + r, j = j0 + tj*4 + c;
            if (i < M && j < N){
                float v = acc[r][c];
                if (bias) v += bias[j];
                C[(size_t)i * N + j] = v;
            }
        }
}

// ---------- persistent GRU + fused p_att tail (unchanged) ----------
#define GRU_NCTA 112
#define GRU_THREADS 672
#define GRU_JPC 7
__global__ void __launch_bounds__(GRU_THREADS)
k_gru_all(const float* __restrict__ Whh, const float* __restrict__ bhh,
          const float* __restrict__ Wp){
    __shared__ __align__(16) float4 hs4[B_ * (H_ / 4)];
    __shared__ float gsum[GRU_JPC][3][B_];
    int tid = threadIdx.x, wid = tid >> 5, lane = tid & 31;
    int jj = wid / 3, g = wid % 3;
    int j = blockIdx.x * GRU_JPC + jj;
    const float4* w = reinterpret_cast<const float4*>(Whh + (size_t)(g * H_ + j) * H_);
    float bj[3];
    if (tid < GRU_JPC * B_){
        int j2 = blockIdx.x * GRU_JPC + tid / B_;
        bj[0] = bhh[j2]; bj[1] = bhh[H_ + j2]; bj[2] = bhh[2 * H_ + j2];
    }

    for (int s = 0; s < S_; s++){
        const float* hin = g_h[s & 1];
        float* hout = g_h[(s + 1) & 1];

        if (s > 0){
            const float4* src = reinterpret_cast<const float4*>(hin);
            for (int i = tid; i < B_ * (H_ / 4); i += GRU_THREADS) hs4[i] = src[i];
        }
        __syncthreads();

        float red[B_];
        #pragma unroll
        for (int b = 0; b < B_; b++) red[b] = 0.0f;

        if (s > 0){
            float4 wv[7];
            #pragma unroll
            for (int it = 0; it < 7; it++){
                int k4 = lane + it * 32;
                if (it < 6 || lane < 4) wv[it] = w[k4];
                else                    wv[it] = make_float4(0.f, 0.f, 0.f, 0.f);
            }
            unsigned long long acc[B_];
            #pragma unroll
            for (int b = 0; b < B_; b++) acc[b] = 0ULL;
            #pragma unroll
            for (int it = 0; it < 7; it++){
                int k4 = lane + it * 32;
                bool ok = (it < 6 || lane < 4);
                unsigned long long wl = pack2(wv[it].x, wv[it].y);
                unsigned long long wh = pack2(wv[it].z, wv[it].w);
                if (ok){
                    #pragma unroll
                    for (int b = 0; b < B_; b++){
                        float4 h4 = hs4[b * (H_ / 4) + k4];
                        fma2(acc[b], wl, pack2(h4.x, h4.y));
                        fma2(acc[b], wh, pack2(h4.z, h4.w));
                    }
                }
            }
            #pragma unroll
            for (int b = 0; b < B_; b++){
                float x, y; unpack2(acc[b], x, y);
                red[b] = x + y;
            }
            #pragma unroll
            for (int o = 16; o; o >>= 1)
                #pragma unroll
                for (int b = 0; b < B_; b++)
                    red[b] += __shfl_down_sync(0xffffffffu, red[b], o);
        }
        if (lane == 0){
            #pragma unroll
            for (int b = 0; b < B_; b++) gsum[jj][g][b] = red[b];
        }
        __syncthreads();

        if (tid < GRU_JPC * B_){
            int jj2 = tid / B_, b = tid % B_;
            int j2 = blockIdx.x * GRU_JPC + jj2;
            int bs = b * S_ + s;
            const float* gi = g_GI + (size_t)bs * (3 * H_);
            const float* hsf = reinterpret_cast<const float*>(hs4);
            float r = sigm(gi[j2] + gsum[jj2][0][b] + bj[0]);
            float z = sigm(gi[H_ + j2] + gsum[jj2][1][b] + bj[1]);
            float n = tanhf(gi[2 * H_ + j2] + r * (gsum[jj2][2][b] + bj[2]));
            float hold = (s > 0) ? hsf[b * H_ + j2] : 0.0f;
            float hn = (1.0f - z) * n + z * hold;
            hout[b * H_ + j2] = hn;
            g_pref[(size_t)bs * H_ + j2] = hn;
        }

        __threadfence();
        __syncthreads();
        if (tid == 0){
            atomicAdd(&g_bar, 1u);
            unsigned target = (unsigned)GRU_NCTA * (unsigned)(s + 1);
            while (*((volatile unsigned*)&g_bar) < target) { }
        }
        __syncthreads();
        __threadfence();
    }

    // fused p_att tail
    float* prow = reinterpret_cast<float*>(hs4);
    int bsl[3]; int nbs = 0;
    for (int r = blockIdx.x; r < BSN; r += GRU_NCTA) bsl[nbs++] = r;
    __syncthreads();
    for (int i = tid; i < nbs * H_; i += GRU_THREADS){
        int r = i / H_, k = i - r * H_;
        prow[r * H_ + k] = g_pref[(size_t)bsl[r] * H_ + k];
    }
    __syncthreads();

    for (int m = wid; m < M_; m += (GRU_THREADS / 32)){
        const float4* wr = reinterpret_cast<const float4*>(Wp + (size_t)m * H_);
        float a[3] = {0.f, 0.f, 0.f};
        for (int k4 = lane; k4 < H_ / 4; k4 += 32){
            float4 w4 = wr[k4];
            for (int r = 0; r < nbs; r++){
                float4 p4 = reinterpret_cast<const float4*>(prow + r * H_)[k4];
                a[r] += p4.x * w4.x + p4.y * w4.y + p4.z * w4.z + p4.w * w4.w;
            }
        }
        #pragma unroll
        for (int o = 16; o; o >>= 1)
            for (int r = 0; r < 3; r++)
                a[r] += __shfl_down_sync(0xffffffffu, a[r], o);
        if (lane == 0)
            for (int r = 0; r < nbs; r++)
                g_patt[(size_t)bsl[r] * M_ + m] = a[r];
    }
}

// ---------- k_att: tensor-core, TRUE smem double-buffered pipeline ----------
// Per chunk: store chunk k+1 into buf^1 while MMAing chunk k from buf;
// ONE __syncthreads per chunk. A-lo ldsm hoisted ahead of the MMA chain.
#define ATT_THREADS 896
__global__ void __launch_bounds__(ATT_THREADS, 1)
k_att(const float* __restrict__ video, const float* __restrict__ Wv_b,
      const float* __restrict__ Wpv, const float* __restrict__ conv_w,
      const float* __restrict__ conv_b){
    extern __shared__ char dsm[];
    __shared__ float cw[4 * C_];
    __shared__ float sc2[4 * 224];
    __shared__ float sc[NSP];
    __shared__ float attb[NSP];
    __shared__ float wS[28][8];

    int t = blockIdx.x;
    int bs = t / P_;
    const float* V = video + (size_t)t * (C_ * NSP);
    int tid = threadIdx.x;
    int w = tid >> 5, lane = tid & 31;
    int nt = w % 7, mt = w / 7;
    int n0w = nt * 32, m0w = mt * 32;
    uint32_t sbase = smem_u32(dsm);

    for (int i = tid; i < 4 * C_; i += ATT_THREADS) cw[i] = conv_w[i];

    // zero the n-pad region of both V buffers, both splits (persists)
    for (int i = tid; i < 2 * 2 * 16 * 36; i += ATT_THREADS){
        int b = i / 1152, rem = i % 1152;
        int sp = rem / 576, rem2 = rem % 576;
        int c = rem2 / 36, nn = 196 + rem2 % 36;
        *reinterpret_cast<__nv_bfloat16*>(dsm + b * BUFSZ + sp * VL_OFF + (c * NPAD + nn) * 2)
            = __float2bfloat16(0.0f);
    }

    bool vvalid = (tid < 784);
    int vc = tid / 49, vnb = tid % 49;
    int widx0 = tid, widx1 = tid + 896, widx2 = tid + 1792;
    const uint32_t* WHg = reinterpret_cast<const uint32_t*>(g_Wh);
    const uint32_t* WLg = reinterpret_cast<const uint32_t*>(g_Wl);

    int matA = lane >> 3;
    uint32_t a_local = (uint32_t)(((lane & 7) + (matA >> 1) * 8) * NPAD + n0w + (matA & 1) * 8) * 2;
    int matB = lane >> 3;
    uint32_t b_local = (uint32_t)((m0w + (matB >> 1) * 8 + (lane & 7)) * WPAD) * 2 + (matB & 1) * 16;

    float4 vreg = make_float4(0.f, 0.f, 0.f, 0.f);
    uint32_t wreg0 = 0, wreg1 = 0, wreg2 = 0;

    auto load_chunk = [&](int kn){
        if (vvalid) vreg = *reinterpret_cast<const float4*>(V + (kn * KC + vc) * NSP + vnb * 4);
        {
            int half = widx0 >> 10, wi = widx0 & 1023, m = wi >> 3, k2 = wi & 7;
            wreg0 = (half ? WLg : WHg)[m * 264 + kn * 8 + k2];
        }
        {
            int half = widx1 >> 10, wi = widx1 & 1023, m = wi >> 3, k2 = wi & 7;
            wreg1 = (half ? WLg : WHg)[m * 264 + kn * 8 + k2];
        }
        if (widx2 < 2048){
            int half = widx2 >> 10, wi = widx2 & 1023, m = wi >> 3, k2 = wi & 7;
            wreg2 = (half ? WLg : WHg)[m * 264 + kn * 8 + k2];
        }
    };
    auto store_chunk = [&](char* sb){
        if (vvalid){
            __nv_bfloat16 h0 = __float2bfloat16(vreg.x);
            __nv_bfloat16 h1 = __float2bfloat16(vreg.y);
            __nv_bfloat16 h2 = __float2bfloat16(vreg.z);
            __nv_bfloat16 h3 = __float2bfloat16(vreg.w);
            float l0 = vreg.x - __bfloat162float(h0);
            float l1 = vreg.y - __bfloat162float(h1);
            float l2 = vreg.z - __bfloat162float(h2);
            float l3 = vreg.w - __bfloat162float(h3);
            uint32_t hu0, hu1;
            { __nv_bfloat162 p = __halves2bfloat162(h0, h1); hu0 = *reinterpret_cast<uint32_t*>(&p); }
            { __nv_bfloat162 p = __halves2bfloat162(h2, h3); hu1 = *reinterpret_cast<uint32_t*>(&p); }
            *reinterpret_cast<uint2*>(sb + VH_OFF + (vc * NPAD + vnb * 4) * 2) = make_uint2(hu0, hu1);
            *reinterpret_cast<uint2*>(sb + VL_OFF + (vc * NPAD + vnb * 4) * 2) =
                make_uint2(packbf(l0, l1), packbf(l2, l3));
        }
        {
            int half = widx0 >> 10, wi = widx0 & 1023, m = wi >> 3, k2 = wi & 7;
            reinterpret_cast<uint32_t*>(sb + (half ? WL_OFF : WH_OFF))[m * 12 + k2] = wreg0;
        }
        {
            int half = widx1 >> 10, wi = widx1 & 1023, m = wi >> 3, k2 = wi & 7;
            reinterpret_cast<uint32_t*>(sb + (half ? WL_OFF : WH_OFF))[m * 12 + k2] = wreg1;
        }
        if (widx2 < 2048){
            int half = widx2 >> 10, wi = widx2 & 1023, m = wi >> 3, k2 = wi & 7;
            reinterpret_cast<uint32_t*>(sb + (half ? WL_OFF : WH_OFF))[m * 12 + k2] = wreg2;
        }
    };

    float dacc[2][4][4];
    #pragma unroll
    for (int i = 0; i < 2; i++)
        #pragma unroll
        for (int j = 0; j < 4; j++)
            #pragma unroll
            for (int k = 0; k < 4; k++) dacc[i][j][k] = 0.0f;

    // prologue: chunk0 -> buf0; prefetch chunk1 into regs
    load_chunk(0);
    store_chunk(dsm);
    if (NCHUNK > 1) load_chunk(1);
    __syncthreads();

    for (int kc = 0; kc < NCHUNK; kc++){
        int buf = kc & 1;
        // store chunk kc+1 (in regs) into the other buffer — overlaps with MMA
        if (kc + 1 < NCHUNK) store_chunk(dsm + (buf ^ 1) * BUFSZ);
        // prefetch chunk kc+2
        if (kc + 2 < NCHUNK) load_chunk(kc + 2);

        // MMA on current buffer
        uint32_t sbb = sbase + buf * BUFSZ;
        uint32_t bh[8], bl[8];
        ldsm4(bh,     sbb + WH_OFF + b_local);
        ldsm4(bh + 4, sbb + WH_OFF + b_local + 16 * WPAD * 2);
        ldsm4(bl,     sbb + WL_OFF + b_local);
        ldsm4(bl + 4, sbb + WL_OFF + b_local + 16 * WPAD * 2);
        #pragma unroll
        for (int nsub = 0; nsub < 2; nsub++){
            uint32_t ah[4], al[4];
            ldsm4t(ah, sbb + VH_OFF + a_local + nsub * 32);
            ldsm4t(al, sbb + VL_OFF + a_local + nsub * 32);
            #pragma unroll
            for (int ms = 0; ms < 4; ms++) mma_bf16(dacc[nsub][ms], ah, bh + ms * 2);
            #pragma unroll
            for (int ms = 0; ms < 4; ms++) mma_bf16(dacc[nsub][ms], ah, bl + ms * 2);
            #pragma unroll
            for (int ms = 0; ms < 4; ms++) mma_bf16(dacc[nsub][ms], al, bh + ms * 2);
        }
        __syncthreads();
    }

    // ---- epilogue: scores ----
    const float* pa = g_patt + (size_t)bs * M_;
    float rs[2][2] = {{0.f, 0.f}, {0.f, 0.f}};
    #pragma unroll
    for (int nsub = 0; nsub < 2; nsub++)
        #pragma unroll
        for (int ms = 0; ms < 4; ms++){
            int m0 = m0w + ms * 8 + 2 * (lane & 3);
            float pv0 = pa[m0] + Wv_b[m0], pv1 = pa[m0 + 1] + Wv_b[m0 + 1];
            float w0 = Wpv[m0], w1 = Wpv[m0 + 1];
            const float* d = dacc[nsub][ms];
            rs[nsub][0] += tanh_fast(d[0] + pv0) * w0 + tanh_fast(d[1] + pv1) * w1;
            rs[nsub][1] += tanh_fast(d[2] + pv0) * w0 + tanh_fast(d[3] + pv1) * w1;
        }
    #pragma unroll
    for (int o = 1; o <= 2; o <<= 1)
        #pragma unroll
        for (int nsub = 0; nsub < 2; nsub++)
            #pragma unroll
            for (int h = 0; h < 2; h++)
                rs[nsub][h] += __shfl_xor_sync(0xffffffffu, rs[nsub][h], o);
    if ((lane & 3) == 0){
        int la = lane >> 2;
        #pragma unroll
        for (int nsub = 0; nsub < 2; nsub++)
            #pragma unroll
            for (int h = 0; h < 2; h++)
                sc2[mt * 224 + n0w + nsub * 16 + h * 8 + la] = rs[nsub][h];
    }
    __syncthreads();
    if (tid < NSP)
        sc[tid] = sc2[tid] + sc2[224 + tid] + sc2[448 + tid] + sc2[672 + tid];
    __syncthreads();

    if (tid < 32){
        float mx = -3.4e38f;
        for (int n = tid; n < NSP; n += 32) mx = fmaxf(mx, sc[n]);
        #pragma unroll
        for (int o = 16; o; o >>= 1) mx = fmaxf(mx, __shfl_xor_sync(0xffffffffu, mx, o));
        float sm = 0.0f;
        for (int n = tid; n < NSP; n += 32){ float e = expf(sc[n] - mx); attb[n] = e; sm += e; }
        #pragma unroll
        for (int o = 16; o; o >>= 1) sm += __shfl_xor_sync(0xffffffffu, sm, o);
        float inv = 1.0f / sm;
        for (int n = tid; n < NSP; n += 32) attb[n] *= inv;
    }
    __syncthreads();

    float d0 = 0.f, d1 = 0.f, d2 = 0.f, d3 = 0.f;
    int n = tid >> 1, half = tid & 1;
    if (tid < 392){
        const float4* fp = reinterpret_cast<const float4*>(V + (size_t)n * C_ + half * 264);
        #pragma unroll 4
        for (int q = 0; q < 66; q++){
            float4 v4 = fp[q];
            int c = half * 264 + q * 4;
            d0 += v4.x*cw[c]       + v4.y*cw[c+1]       + v4.z*cw[c+2]       + v4.w*cw[c+3];
            d1 += v4.x*cw[528+c]   + v4.y*cw[528+c+1]   + v4.z*cw[528+c+2]   + v4.w*cw[528+c+3];
            d2 += v4.x*cw[1056+c]  + v4.y*cw[1056+c+1]  + v4.z*cw[1056+c+2]  + v4.w*cw[1056+c+3];
            d3 += v4.x*cw[1584+c]  + v4.y*cw[1584+c+1]  + v4.z*cw[1584+c+2]  + v4.w*cw[1584+c+3];
        }
    }
    d0 += __shfl_xor_sync(0xffffffffu, d0, 1);
    d1 += __shfl_xor_sync(0xffffffffu, d1, 1);
    d2 += __shfl_xor_sync(0xffffffffu, d2, 1);
    d3 += __shfl_xor_sync(0xffffffffu, d3, 1);

    float dsum[4] = {0,0,0,0}, dsq[4] = {0,0,0,0};
    if (tid < 392 && half == 0){
        float an = attb[n];
        float vv[4];
        vv[0] = an * d0 + conv_b[0];
        vv[1] = an * d1 + conv_b[1];
        vv[2] = an * d2 + conv_b[2];
        vv[3] = an * d3 + conv_b[3];
        #pragma unroll
        for (int o = 0; o < 4; o++){
            g_vidpre[(size_t)t * 784 + o * NSP + n] = vv[o];
            dsum[o] = vv[o];
            dsq[o] = vv[o] * vv[o];
        }
    }
    #pragma unroll
    for (int o = 0; o < 4; o++){
        #pragma unroll
        for (int sh = 16; sh; sh >>= 1){
            dsum[o] += __shfl_down_sync(0xffffffffu, dsum[o], sh);
            dsq[o]  += __shfl_down_sync(0xffffffffu, dsq[o], sh);
        }
    }
    if (lane == 0){
        #pragma unroll
        for (int o = 0; o < 4; o++){ wS[w][o] = dsum[o]; wS[w][4 + o] = dsq[o]; }
    }
    __syncthreads();
    if (tid < 8){
        float a = 0.f;
        #pragma unroll
        for (int ww = 0; ww < 28; ww++) a += wS[ww][tid];
        g_bnPart[t * 8 + tid] = a;
    }
}

// ---------- motion BN stats ----------
__global__ void k_mstats(){
    int m = threadIdx.x;
    float sum = 0.f, sq = 0.f;
    for (int r = 0; r < BSN; r++){
        float v = g_mot[r * M_ + m];
        sum += v; sq += v * v;
    }
    float mu = sum / (float)BSN;
    float var = sq / (float)BSN - mu * mu;
    g_mstats[m] = mu;
    g_mstats[M_ + m] = rsqrtf(var + 1e-5f);
}

// ---------- video BN stats reduce ----------
__global__ void k_vstats(){
    __shared__ float red[256];
    __shared__ float tot[8];
    int tid = threadIdx.x;
    float part[8] = {0,0,0,0,0,0,0,0};
    for (int t = tid; t < TOT; t += 256)
        #pragma unroll
        for (int k = 0; k < 8; k++) part[k] += g_bnPart[t * 8 + k];
    for (int k = 0; k < 8; k++){
        red[tid] = part[k];
        __syncthreads();
        for (int o = 128; o; o >>= 1){
            if (tid < o) red[tid] += red[tid + o];
            __syncthreads();
        }
        if (tid == 0) tot[k] = red[0];
        __syncthreads();
    }
    if (tid < 4){
        float cnt = (float)TOT * (float)NSP;
        float mu = tot[tid] / cnt;
        float var = tot[4 + tid] / cnt - mu * mu;
        g_vstats[tid] = mu;
        g_vstats[4 + tid] = rsqrtf(var + 1e-5f);
    }
}

// ---------- final assembly ----------
__global__ void k_final(const float* __restrict__ tw,
                        const float* __restrict__ vbn_g, const float* __restrict__ vbn_b,
                        const float* __restrict__ mbn_g, const float* __restrict__ mbn_b,
                        float* __restrict__ out){
    int t = blockIdx.x, bs = t / P_, p = t % P_;
    float* o = out + (size_t)t * OUTW;
    for (int c = threadIdx.x; c < OUTW; c += 256){
        float v;
        if (c == 0) v = tw[p];
        else if (c < 785) v = g_pref[(size_t)bs * H_ + (c - 1)];
        else if (c < 913){
            int m = c - 785;
            float x = g_mot[bs * M_ + m];
            v = fmaxf((x - g_mstats[m]) * g_mstats[M_ + m] * mbn_g[m] + mbn_b[m], 0.f);
        } else {
            int idx = c - 913, ch = idx / NSP;
            float x = g_vidpre[(size_t)t * 784 + idx];
            v = fmaxf((x - g_vstats[ch]) * g_vstats[4 + ch] * vbn_g[ch] + vbn_b[ch], 0.f);
        }
        o[c] = v;
    }
}

// ---------- launcher ----------
extern "C" void kernel_launch(void* const* d_in, const int* in_sizes, int n_in,
                              void* d_out, int out_size){
    const float* fov      = (const float*)d_in[0];
    const float* motion   = (const float*)d_in[1];
    const float* video    = (const float*)d_in[2];
    const float* timew    = (const float*)d_in[3];
    const float* gru_w_ih = (const float*)d_in[4];
    const float* gru_w_hh = (const float*)d_in[5];
    const float* gru_b_ih = (const float*)d_in[6];
    const float* gru_b_hh = (const float*)d_in[7];
    const float* Wp       = (const float*)d_in[8];
    const float* Wv_w     = (const float*)d_in[9];
    const float* Wv_b     = (const float*)d_in[10];
    const float* Wpv_w    = (const float*)d_in[11];
    const float* conv_w   = (const float*)d_in[13];
    const float* conv_b   = (const float*)d_in[14];
    const float* vbn_g    = (const float*)d_in[15];
    const float* vbn_b    = (const float*)d_in[16];
    const float* me_w     = (const float*)d_in[17];
    const float* me_b     = (const float*)d_in[18];
    const float* mbn_g    = (const float*)d_in[19];
    const float* mbn_b    = (const float*)d_in[20];
    float* out = (float*)d_out;

    static bool attr_done = false;
    if (!attr_done){
        cudaFuncSetAttribute(k_att, cudaFuncAttributeMaxDynamicSharedMemorySize, ATT_DSMEM);
        attr_done = true;
    }

    k_prep<<<264, 256>>>(Wv_w);                                              // 1
    k_gemm_nt<<<dim3(37, 8), 256>>>(fov, gru_w_ih, gru_b_ih, 0,
                                    BSN, 3 * H_, C_);                        // 2
    k_gru_all<<<GRU_NCTA, GRU_THREADS>>>(gru_w_hh, gru_b_hh, Wp);            // 3
    k_att<<<TOT, ATT_THREADS, ATT_DSMEM>>>(video, Wv_b, Wpv_w,
                                           conv_w, conv_b);                  // 4 -> ncu
    k_gemm_nt<<<dim3(2, 8), 256>>>(motion, me_w, me_b, 2, BSN, M_, 90);      // 5
    k_mstats<<<1, 128>>>();
    k_vstats<<<1, 256>>>();
    k_final<<<TOT, 256>>>(timew, vbn_g, vbn_b, mbn_g, mbn_b, out);
}